// round 11
// baseline (speedup 1.0000x reference)
#include <cuda_runtime.h>
#include <cuda_bf16.h>
#include <cstdint>
#include <cstddef>

#define BB 256
#define TT 512
#define II 128
#define HH 256
#define GG 768

typedef unsigned long long u64;

__device__ float g_xg[(size_t)BB * TT * GG];

// ---------------- bf16 helpers ----------------
__device__ __forceinline__ uint32_t pkbf(float x, float y) {
    __nv_bfloat162 h = __floats2bfloat162_rn(x, y);
    return *(uint32_t*)&h;
}
__device__ __forceinline__ float bfres(float x) {   // x - bf16(x)
    return x - __bfloat162float(__float2bfloat16(x));
}
__device__ __forceinline__ void ldsm_x4(uint32_t& r0, uint32_t& r1,
                                        uint32_t& r2, uint32_t& r3, uint32_t a) {
    asm volatile("ldmatrix.sync.aligned.m8n8.x4.shared.b16 {%0,%1,%2,%3}, [%4];"
                 : "=r"(r0), "=r"(r1), "=r"(r2), "=r"(r3) : "r"(a));
}
__device__ __forceinline__ void ldsm_x2t(uint32_t& r0, uint32_t& r1, uint32_t a) {
    asm volatile("ldmatrix.sync.aligned.m8n8.x2.trans.shared.b16 {%0,%1}, [%2];"
                 : "=r"(r0), "=r"(r1) : "r"(a));
}
__device__ __forceinline__ void mma16816(float& c0, float& c1, float& c2, float& c3,
                                         uint32_t a0, uint32_t a1, uint32_t a2, uint32_t a3,
                                         uint32_t b0, uint32_t b1) {
    asm("mma.sync.aligned.m16n8k16.row.col.f32.bf16.bf16.f32 "
        "{%0,%1,%2,%3}, {%4,%5,%6,%7}, {%8,%9}, {%0,%1,%2,%3};"
        : "+f"(c0), "+f"(c1), "+f"(c2), "+f"(c3)
        : "r"(a0), "r"(a1), "r"(a2), "r"(a3), "r"(b0), "r"(b1));
}

// ---------------------------------------------------------------------------
// Phase 1 (frozen, ~284us): xg = x @ W_ih^T + b_ih, HMMA bf16-split.
// ---------------------------------------------------------------------------
#define SM1_AHI 0
#define SM1_ALO 32768
#define SM1_BHI 65536
#define SM1_BLO 81920
#define SM1_BYTES 98304

__global__ __launch_bounds__(256, 2) void xg_mma_kernel(
    const float* __restrict__ x,
    const float* __restrict__ Wih,
    const float* __restrict__ bih)
{
    extern __shared__ char sm1[];
    const uint32_t smb = (uint32_t)__cvta_generic_to_shared(sm1);
    const int tid  = threadIdx.x;
    const int warp = tid >> 5;
    const int lane = tid & 31;
    const int bn = blockIdx.x;
    const int bm = blockIdx.y;

    {
        const float* xr = x + (size_t)bm * 128 * II;
        const int r_ = tid >> 5, kq = tid & 31;
        const uint32_t off0 = (uint32_t)((((kq >> 1) ^ (r_ & 7)) << 4) + (kq & 1) * 8);
#pragma unroll
        for (int i = 0; i < 16; ++i) {
            int r = r_ + i * 8;
            float4 v = *(const float4*)(xr + (size_t)r * II + kq * 4);
            uint2 hi = make_uint2(pkbf(v.x, v.y), pkbf(v.z, v.w));
            uint2 lo = make_uint2(pkbf(bfres(v.x), bfres(v.y)),
                                  pkbf(bfres(v.z), bfres(v.w)));
            uint32_t off = (uint32_t)(r * 256) + off0;
            *(uint2*)(sm1 + SM1_AHI + off) = hi;
            *(uint2*)(sm1 + SM1_ALO + off) = lo;
        }
        const float* wr = Wih + (size_t)bn * 64 * II;
#pragma unroll
        for (int i = 0; i < 8; ++i) {
            int n = r_ + i * 8;
            float4 v = *(const float4*)(wr + (size_t)n * II + kq * 4);
            uint2 hi = make_uint2(pkbf(v.x, v.y), pkbf(v.z, v.w));
            uint2 lo = make_uint2(pkbf(bfres(v.x), bfres(v.y)),
                                  pkbf(bfres(v.z), bfres(v.w)));
            uint32_t off = (uint32_t)(n * 256) + off0;
            *(uint2*)(sm1 + SM1_BHI + off) = hi;
            *(uint2*)(sm1 + SM1_BLO + off) = lo;
        }
    }
    __syncthreads();

    const int mr2 = warp >> 1;
    const int nc2 = warp & 1;
    const uint32_t lrow  = (uint32_t)(lane & 15);
    const uint32_t khalf = (uint32_t)(lane >> 4);
    const uint32_t r7    = lrow & 7u;
    const uint32_t aRB = smb + SM1_AHI + (uint32_t)(mr2 * 32 + lrow) * 256u;
    const uint32_t bRB = smb + SM1_BHI + (uint32_t)(nc2 * 32 + lrow) * 256u;

    float c[2][4][4];
#pragma unroll
    for (int m = 0; m < 2; ++m)
#pragma unroll
        for (int n = 0; n < 4; ++n)
#pragma unroll
            for (int q = 0; q < 4; ++q) c[m][n][q] = 0.f;

#pragma unroll
    for (int kt = 0; kt < 8; ++kt) {
        const uint32_t swz = (((uint32_t)(kt * 2) + khalf) ^ r7) << 4;
        uint32_t ah[2][4], al[2][4], bh[2][4], bl[2][4];
#pragma unroll
        for (int m = 0; m < 2; ++m) {
            uint32_t a = aRB + (uint32_t)(m * 4096) + swz;
            ldsm_x4(ah[m][0], ah[m][1], ah[m][2], ah[m][3], a);
            ldsm_x4(al[m][0], al[m][1], al[m][2], al[m][3], a + 32768u);
        }
#pragma unroll
        for (int nn = 0; nn < 2; ++nn) {
            uint32_t b = bRB + (uint32_t)(nn * 4096) + swz;
            ldsm_x4(bh[nn][0], bh[nn][1], bh[nn][2], bh[nn][3], b);
            ldsm_x4(bl[nn][0], bl[nn][1], bl[nn][2], bl[nn][3], b + 16384u);
        }
#pragma unroll
        for (int m = 0; m < 2; ++m) {
#pragma unroll
            for (int nn = 0; nn < 2; ++nn) {
                float* c0 = c[m][nn * 2];
                float* c1 = c[m][nn * 2 + 1];
                mma16816(c0[0], c0[1], c0[2], c0[3],
                         ah[m][0], ah[m][1], ah[m][2], ah[m][3],
                         bh[nn][0], bh[nn][2]);
                mma16816(c1[0], c1[1], c1[2], c1[3],
                         ah[m][0], ah[m][1], ah[m][2], ah[m][3],
                         bh[nn][1], bh[nn][3]);
                mma16816(c0[0], c0[1], c0[2], c0[3],
                         ah[m][0], ah[m][1], ah[m][2], ah[m][3],
                         bl[nn][0], bl[nn][2]);
                mma16816(c1[0], c1[1], c1[2], c1[3],
                         ah[m][0], ah[m][1], ah[m][2], ah[m][3],
                         bl[nn][1], bl[nn][3]);
                mma16816(c0[0], c0[1], c0[2], c0[3],
                         al[m][0], al[m][1], al[m][2], al[m][3],
                         bh[nn][0], bh[nn][2]);
                mma16816(c1[0], c1[1], c1[2], c1[3],
                         al[m][0], al[m][1], al[m][2], al[m][3],
                         bh[nn][1], bh[nn][3]);
            }
        }
    }

    const int gq = lane >> 2, tq = lane & 3;
#pragma unroll
    for (int nf = 0; nf < 4; ++nf) {
        int col = bn * 64 + nc2 * 32 + nf * 8 + tq * 2;
        float2 bb = *(const float2*)(bih + col);
#pragma unroll
        for (int m = 0; m < 2; ++m) {
            int row = bm * 128 + mr2 * 32 + m * 16 + gq;
            float2 o0 = make_float2(c[m][nf][0] + bb.x, c[m][nf][1] + bb.y);
            float2 o1 = make_float2(c[m][nf][2] + bb.x, c[m][nf][3] + bb.y);
            *(float2*)(g_xg + (size_t)row * GG + col) = o0;
            *(float2*)(g_xg + (size_t)(row + 8) * GG + col) = o1;
        }
    }
}

// ---------------------------------------------------------------------------
// Phase 2: dual-stream pipelined HMMA recurrence. 32 clusters x 4 CTAs.
// Stream A = batches 0-3 of the group, stream B = batches 4-7. While one
// stream's h-exchange drains across the cluster, the other stream computes.
// B operand row (16B) = [b0hi b0lo b1hi b1lo b2hi b2lo b3hi b3lo]: hi/lo as
// n-columns; epilogue adds column pairs (full 4-term bf16-split product).
// ---------------------------------------------------------------------------
#define TPB2 384

#define OFF_W1   0                        // 12*16*32*16 = 98304
#define OFF_W2   98304                    // 98304
#define OFF_HA   196608                   // 2 phases * 256 * 16 = 8192
#define OFF_HB   204800                   // 8192
#define OFF_PSA  212992                   // 192*4*4 = 3072
#define OFF_PSB  216064                   // 3072
#define OFF_BSM  219136                   // 768
#define OFF_MBA  219904                   // 8
#define OFF_MBB  219912                   // 8
#define SM2_BYTES 219968

__device__ __forceinline__ void mbar_waitc(uint32_t mbar, uint32_t parity) {
    uint32_t done;
    asm volatile(
        "{\n\t.reg .pred p;\n\t"
        "mbarrier.try_wait.parity.acquire.cluster.shared::cta.b64 p, [%1], %2;\n\t"
        "selp.b32 %0, 1, 0, p;\n\t}"
        : "=r"(done) : "r"(mbar), "r"(parity) : "memory");
    if (!done) {
        asm volatile(
            "{\n\t.reg .pred P1;\n\t"
            "W%=:\n\t"
            "mbarrier.try_wait.parity.acquire.cluster.shared::cta.b64 P1, [%0], %1, 0x989680;\n\t"
            "@P1 bra.uni D%=;\n\t"
            "bra.uni W%=;\n\t"
            "D%=:\n\t}"
            :: "r"(mbar), "r"(parity) : "memory");
    }
}

struct GemmOut { float d0, d1; };   // d0 = row gq value, d1 = row gq+8 value

__device__ __forceinline__ GemmOut gemm_stream(
    const char* w1p, const char* w2p, uint32_t hbase, int kln)
{
    float ch[4][4];
#pragma unroll
    for (int i = 0; i < 4; ++i)
#pragma unroll
        for (int q = 0; q < 4; ++q) ch[i][q] = 0.f;
#pragma unroll
    for (int kt = 0; kt < 16; ++kt) {
        uint4 w1 = *(const uint4*)(w1p + kt * 512);
        uint4 w2 = *(const uint4*)(w2p + kt * 512);
        uint32_t addr = hbase + (uint32_t)((kt * 16 + kln) * 16);
        uint32_t b0, b1;
        ldsm_x2t(b0, b1, addr);
        float* cA = ch[kt & 1];
        float* cB = ch[2 + (kt & 1)];
        mma16816(cA[0], cA[1], cA[2], cA[3], w1.x, w1.y, w1.z, w1.w, b0, b1);
        mma16816(cB[0], cB[1], cB[2], cB[3], w2.x, w2.y, w2.z, w2.w, b0, b1);
    }
    GemmOut o;
    // cols 2tq (hi) + 2tq+1 (lo) summed -> full value for batch tq
    o.d0 = ((ch[0][0] + ch[1][0]) + (ch[2][0] + ch[3][0]))
         + ((ch[0][1] + ch[1][1]) + (ch[2][1] + ch[3][1]));
    o.d1 = ((ch[0][2] + ch[1][2]) + (ch[2][2] + ch[3][2]))
         + ((ch[0][3] + ch[1][3]) + (ch[2][3] + ch[3][3]));
    return o;
}

__global__ __launch_bounds__(TPB2, 1) __cluster_dims__(4, 1, 1)
void gru_seq_mma(const float* __restrict__ Whh,
                 const float* __restrict__ bhh,
                 float* __restrict__ out)
{
    extern __shared__ char smem[];
    const uint32_t smb = (uint32_t)__cvta_generic_to_shared(smem);
    float* psA = (float*)(smem + OFF_PSA);
    float* psB = (float*)(smem + OFF_PSB);
    float* bsm = (float*)(smem + OFF_BSM);

    const int tid  = threadIdx.x;
    const int wid  = tid >> 5;
    const int lane = tid & 31;
    const int gq   = lane >> 2;
    const int tq   = lane & 3;
    uint32_t srank;
    asm("mov.u32 %0, %%cluster_ctarank;" : "=r"(srank));
    const int s = (int)srank;
    const int g = blockIdx.x >> 2;

    // ---- init: W1/W2 fragments -> SMEM (A-operand m16k16 frags per warp) ----
    {
        const int r0g = ((wid * 16 + gq) >> 6 << 8) + (s << 6) + ((wid * 16 + gq) & 63);
        const int r1g = ((wid * 16 + gq + 8) >> 6 << 8) + (s << 6) + ((wid * 16 + gq + 8) & 63);
        const float* W0 = Whh + (size_t)r0g * 256;
        const float* W1 = Whh + (size_t)r1g * 256;
#pragma unroll
        for (int kt = 0; kt < 16; ++kt) {
            int c0 = kt * 16 + tq * 2;
            float w00 = W0[c0],     w01 = W0[c0 + 1];
            float w10 = W1[c0],     w11 = W1[c0 + 1];
            float w02 = W0[c0 + 8], w03 = W0[c0 + 9];
            float w12 = W1[c0 + 8], w13 = W1[c0 + 9];
            uint4 w1v, w2v;
            w1v.x = pkbf(w00, w01); w1v.y = pkbf(w10, w11);
            w1v.z = pkbf(w02, w03); w1v.w = pkbf(w12, w13);
            w2v.x = pkbf(bfres(w00), bfres(w01));
            w2v.y = pkbf(bfres(w10), bfres(w11));
            w2v.z = pkbf(bfres(w02), bfres(w03));
            w2v.w = pkbf(bfres(w12), bfres(w13));
            uint32_t o = (uint32_t)(((wid * 16 + kt) * 32 + lane) * 16);
            *(uint4*)(smem + OFF_W1 + o) = w1v;
            *(uint4*)(smem + OFF_W2 + o) = w2v;
        }
    }
    if (tid < 192) {
        int grow = ((tid >> 6) << 8) + (s << 6) + (tid & 63);
        bsm[tid] = bhh[grow];
    }
    for (int i = tid; i < 16384 / 4; i += TPB2)
        ((float*)(smem + OFF_HA))[i] = 0.f;        // zero HA + HB (contiguous)
    if (tid == 0) {
        asm volatile("mbarrier.init.shared.b64 [%0], %1;"
                     :: "r"(smb + OFF_MBA), "r"(4u) : "memory");
        asm volatile("mbarrier.init.shared.b64 [%0], %1;"
                     :: "r"(smb + OFF_MBB), "r"(4u) : "memory");
    }
    __syncthreads();
    asm volatile("barrier.cluster.arrive.aligned;" ::: "memory");
    asm volatile("barrier.cluster.wait.aligned;" ::: "memory");

    const int jj = tid >> 2;              // gate j 0..63 (tid<256)
    const int bb = tid & 3;               // batch within stream
    const int kln = lane & 15;

    float br = 0.f, bz = 0.f, bn_ = 0.f;
    if (tid < 256) { br = bsm[jj]; bz = bsm[64 + jj]; bn_ = bsm[128 + jj]; }

    const uint32_t pushA0 = (uint32_t)(OFF_HA + ((s << 6) + jj) * 16 + bb * 4);
    const uint32_t pushB0 = (uint32_t)(OFF_HB + ((s << 6) + jj) * 16 + bb * 4);

    const char* w1p = smem + OFF_W1 + (size_t)wid * 8192 + lane * 16;
    const char* w2p = smem + OFF_W2 + (size_t)wid * 8192 + lane * 16;

    float hoA = 0.f, hoB = 0.f;

    for (int t = 0; t < TT; ++t) {
        const int p = t & 1;
        const uint32_t wparity = (uint32_t)((t - 1) & 1);

        // prefetch xg(t) for both streams
        float xa0, xa1, xa2, xb0, xb1, xb2;
        if (tid < 256) {
            size_t baseA = ((size_t)(g * 8 + bb) * TT + t) * GG + (s << 6) + jj;
            size_t baseB = baseA + (size_t)4 * TT * GG;
            xa0 = g_xg[baseA]; xa1 = g_xg[baseA + 256]; xa2 = g_xg[baseA + 512];
            xb0 = g_xg[baseB]; xb1 = g_xg[baseB + 256]; xb2 = g_xg[baseB + 512];
        }

        // ================= stream A =================
        if (t) mbar_waitc(smb + OFF_MBA, wparity);
        {
            GemmOut d = gemm_stream(w1p, w2p,
                                    smb + (uint32_t)(OFF_HA + p * 4096), kln);
            psA[(wid * 16 + gq) * 4 + tq]     = d.d0;
            psA[(wid * 16 + gq + 8) * 4 + tq] = d.d1;
        }
        __syncthreads();
        if (tid < 256) {
            float hr = psA[jj * 4 + bb] + br;
            float hz = psA[(64 + jj) * 4 + bb] + bz;
            float hn = psA[(128 + jj) * 4 + bb] + bn_;
            float rg = __fdividef(1.f, 1.f + __expf(-(xa0 + hr)));
            float zg = __fdividef(1.f, 1.f + __expf(-(xa1 + hz)));
            float v  = xa2 + rg * hn;
            float nn = 1.f - 2.f * __fdividef(1.f, __expf(2.f * v) + 1.f);
            float hw = (1.f - zg) * nn + zg * hoA;
            uint32_t val = pkbf(hw, bfres(hw));
            uint32_t la = smb + pushA0 + (uint32_t)((1 - p) * 4096);
#pragma unroll
            for (int rk = 0; rk < 4; ++rk) {
                uint32_t ra;
                asm volatile("mapa.shared::cluster.u32 %0, %1, %2;"
                             : "=r"(ra) : "r"(la), "r"(rk));
                asm volatile("st.shared::cluster.b32 [%0], %1;"
                             :: "r"(ra), "r"(val) : "memory");
            }
            out[((size_t)(g * 8 + bb) * TT + t) * HH + (s << 6) + jj] = hw;
            hoA = hw;
        }
        __syncthreads();
        if (tid == 0) {
            asm volatile("fence.acq_rel.cluster;" ::: "memory");
#pragma unroll
            for (int rk = 0; rk < 4; ++rk) {
                uint32_t ra;
                asm volatile("mapa.shared::cluster.u32 %0, %1, %2;"
                             : "=r"(ra) : "r"(smb + OFF_MBA), "r"(rk));
                asm volatile("mbarrier.arrive.shared::cluster.b64 _, [%0];"
                             :: "r"(ra) : "memory");
            }
        }

        // ================= stream B =================
        if (t) mbar_waitc(smb + OFF_MBB, wparity);
        {
            GemmOut d = gemm_stream(w1p, w2p,
                                    smb + (uint32_t)(OFF_HB + p * 4096), kln);
            psB[(wid * 16 + gq) * 4 + tq]     = d.d0;
            psB[(wid * 16 + gq + 8) * 4 + tq] = d.d1;
        }
        __syncthreads();
        if (tid < 256) {
            float hr = psB[jj * 4 + bb] + br;
            float hz = psB[(64 + jj) * 4 + bb] + bz;
            float hn = psB[(128 + jj) * 4 + bb] + bn_;
            float rg = __fdividef(1.f, 1.f + __expf(-(xb0 + hr)));
            float zg = __fdividef(1.f, 1.f + __expf(-(xb1 + hz)));
            float v  = xb2 + rg * hn;
            float nn = 1.f - 2.f * __fdividef(1.f, __expf(2.f * v) + 1.f);
            float hw = (1.f - zg) * nn + zg * hoB;
            uint32_t val = pkbf(hw, bfres(hw));
            uint32_t la = smb + pushB0 + (uint32_t)((1 - p) * 4096);
#pragma unroll
            for (int rk = 0; rk < 4; ++rk) {
                uint32_t ra;
                asm volatile("mapa.shared::cluster.u32 %0, %1, %2;"
                             : "=r"(ra) : "r"(la), "r"(rk));
                asm volatile("st.shared::cluster.b32 [%0], %1;"
                             :: "r"(ra), "r"(val) : "memory");
            }
            out[((size_t)(g * 8 + 4 + bb) * TT + t) * HH + (s << 6) + jj] = hw;
            hoB = hw;
        }
        __syncthreads();
        if (tid == 0) {
            asm volatile("fence.acq_rel.cluster;" ::: "memory");
#pragma unroll
            for (int rk = 0; rk < 4; ++rk) {
                uint32_t ra;
                asm volatile("mapa.shared::cluster.u32 %0, %1, %2;"
                             : "=r"(ra) : "r"(smb + OFF_MBB), "r"(rk));
                asm volatile("mbarrier.arrive.shared::cluster.b64 _, [%0];"
                             :: "r"(ra) : "memory");
            }
        }
    }

    asm volatile("barrier.cluster.arrive.aligned;" ::: "memory");
    asm volatile("barrier.cluster.wait.aligned;" ::: "memory");
}

// ---------------------------------------------------------------------------
extern "C" void kernel_launch(void* const* d_in, const int* in_sizes, int n_in,
                              void* d_out, int out_size)
{
    const float* x   = (const float*)d_in[0];
    const float* Wih = (const float*)d_in[1];
    const float* Whh = (const float*)d_in[2];
    const float* bih = (const float*)d_in[3];
    const float* bhh = (const float*)d_in[4];
    float* out = (float*)d_out;

    cudaFuncSetAttribute(xg_mma_kernel,
                         cudaFuncAttributeMaxDynamicSharedMemorySize, SM1_BYTES);
    cudaFuncSetAttribute(gru_seq_mma,
                         cudaFuncAttributeMaxDynamicSharedMemorySize, SM2_BYTES);

    dim3 g1(GG / 64, BB * TT / 128);
    xg_mma_kernel<<<g1, 256, SM1_BYTES>>>(x, Wih, bih);
    gru_seq_mma<<<128, TPB2, SM2_BYTES>>>(Whh, bhh, out);
}

// round 12
// speedup vs baseline: 1.3238x; 1.3238x over previous
#include <cuda_runtime.h>
#include <cuda_bf16.h>
#include <cstdint>
#include <cstddef>

#define BB 256
#define TT 512
#define II 128
#define HH 256
#define GG 768

typedef unsigned long long u64;

__device__ float g_xg[(size_t)BB * TT * GG];

// ---------------- bf16 helpers ----------------
__device__ __forceinline__ uint32_t pkbf(float x, float y) {
    __nv_bfloat162 h = __floats2bfloat162_rn(x, y);
    return *(uint32_t*)&h;
}
__device__ __forceinline__ float bfres(float x) {   // x - bf16(x)
    return x - __bfloat162float(__float2bfloat16(x));
}
__device__ __forceinline__ void ldsm_x4(uint32_t& r0, uint32_t& r1,
                                        uint32_t& r2, uint32_t& r3, uint32_t a) {
    asm volatile("ldmatrix.sync.aligned.m8n8.x4.shared.b16 {%0,%1,%2,%3}, [%4];"
                 : "=r"(r0), "=r"(r1), "=r"(r2), "=r"(r3) : "r"(a));
}
__device__ __forceinline__ void ldsm_x2t(uint32_t& r0, uint32_t& r1, uint32_t a) {
    asm volatile("ldmatrix.sync.aligned.m8n8.x2.trans.shared.b16 {%0,%1}, [%2];"
                 : "=r"(r0), "=r"(r1) : "r"(a));
}
__device__ __forceinline__ void mma16816(float& c0, float& c1, float& c2, float& c3,
                                         uint32_t a0, uint32_t a1, uint32_t a2, uint32_t a3,
                                         uint32_t b0, uint32_t b1) {
    asm("mma.sync.aligned.m16n8k16.row.col.f32.bf16.bf16.f32 "
        "{%0,%1,%2,%3}, {%4,%5,%6,%7}, {%8,%9}, {%0,%1,%2,%3};"
        : "+f"(c0), "+f"(c1), "+f"(c2), "+f"(c3)
        : "r"(a0), "r"(a1), "r"(a2), "r"(a3), "r"(b0), "r"(b1));
}

// ---------------------------------------------------------------------------
// Phase 1 (frozen, ~284us): xg = x @ W_ih^T + b_ih, HMMA bf16-split.
// ---------------------------------------------------------------------------
#define SM1_AHI 0
#define SM1_ALO 32768
#define SM1_BHI 65536
#define SM1_BLO 81920
#define SM1_BYTES 98304

__global__ __launch_bounds__(256, 2) void xg_mma_kernel(
    const float* __restrict__ x,
    const float* __restrict__ Wih,
    const float* __restrict__ bih)
{
    extern __shared__ char sm1[];
    const uint32_t smb = (uint32_t)__cvta_generic_to_shared(sm1);
    const int tid  = threadIdx.x;
    const int warp = tid >> 5;
    const int lane = tid & 31;
    const int bn = blockIdx.x;
    const int bm = blockIdx.y;

    {
        const float* xr = x + (size_t)bm * 128 * II;
        const int r_ = tid >> 5, kq = tid & 31;
        const uint32_t off0 = (uint32_t)((((kq >> 1) ^ (r_ & 7)) << 4) + (kq & 1) * 8);
#pragma unroll
        for (int i = 0; i < 16; ++i) {
            int r = r_ + i * 8;
            float4 v = *(const float4*)(xr + (size_t)r * II + kq * 4);
            uint2 hi = make_uint2(pkbf(v.x, v.y), pkbf(v.z, v.w));
            uint2 lo = make_uint2(pkbf(bfres(v.x), bfres(v.y)),
                                  pkbf(bfres(v.z), bfres(v.w)));
            uint32_t off = (uint32_t)(r * 256) + off0;
            *(uint2*)(sm1 + SM1_AHI + off) = hi;
            *(uint2*)(sm1 + SM1_ALO + off) = lo;
        }
        const float* wr = Wih + (size_t)bn * 64 * II;
#pragma unroll
        for (int i = 0; i < 8; ++i) {
            int n = r_ + i * 8;
            float4 v = *(const float4*)(wr + (size_t)n * II + kq * 4);
            uint2 hi = make_uint2(pkbf(v.x, v.y), pkbf(v.z, v.w));
            uint2 lo = make_uint2(pkbf(bfres(v.x), bfres(v.y)),
                                  pkbf(bfres(v.z), bfres(v.w)));
            uint32_t off = (uint32_t)(n * 256) + off0;
            *(uint2*)(sm1 + SM1_BHI + off) = hi;
            *(uint2*)(sm1 + SM1_BLO + off) = lo;
        }
    }
    __syncthreads();

    const int mr2 = warp >> 1;
    const int nc2 = warp & 1;
    const uint32_t lrow  = (uint32_t)(lane & 15);
    const uint32_t khalf = (uint32_t)(lane >> 4);
    const uint32_t r7    = lrow & 7u;
    const uint32_t aRB = smb + SM1_AHI + (uint32_t)(mr2 * 32 + lrow) * 256u;
    const uint32_t bRB = smb + SM1_BHI + (uint32_t)(nc2 * 32 + lrow) * 256u;

    float c[2][4][4];
#pragma unroll
    for (int m = 0; m < 2; ++m)
#pragma unroll
        for (int n = 0; n < 4; ++n)
#pragma unroll
            for (int q = 0; q < 4; ++q) c[m][n][q] = 0.f;

#pragma unroll
    for (int kt = 0; kt < 8; ++kt) {
        const uint32_t swz = (((uint32_t)(kt * 2) + khalf) ^ r7) << 4;
        uint32_t ah[2][4], al[2][4], bh[2][4], bl[2][4];
#pragma unroll
        for (int m = 0; m < 2; ++m) {
            uint32_t a = aRB + (uint32_t)(m * 4096) + swz;
            ldsm_x4(ah[m][0], ah[m][1], ah[m][2], ah[m][3], a);
            ldsm_x4(al[m][0], al[m][1], al[m][2], al[m][3], a + 32768u);
        }
#pragma unroll
        for (int nn = 0; nn < 2; ++nn) {
            uint32_t b = bRB + (uint32_t)(nn * 4096) + swz;
            ldsm_x4(bh[nn][0], bh[nn][1], bh[nn][2], bh[nn][3], b);
            ldsm_x4(bl[nn][0], bl[nn][1], bl[nn][2], bl[nn][3], b + 16384u);
        }
#pragma unroll
        for (int m = 0; m < 2; ++m) {
#pragma unroll
            for (int nn = 0; nn < 2; ++nn) {
                float* c0 = c[m][nn * 2];
                float* c1 = c[m][nn * 2 + 1];
                mma16816(c0[0], c0[1], c0[2], c0[3],
                         ah[m][0], ah[m][1], ah[m][2], ah[m][3],
                         bh[nn][0], bh[nn][2]);
                mma16816(c1[0], c1[1], c1[2], c1[3],
                         ah[m][0], ah[m][1], ah[m][2], ah[m][3],
                         bh[nn][1], bh[nn][3]);
                mma16816(c0[0], c0[1], c0[2], c0[3],
                         ah[m][0], ah[m][1], ah[m][2], ah[m][3],
                         bl[nn][0], bl[nn][2]);
                mma16816(c1[0], c1[1], c1[2], c1[3],
                         ah[m][0], ah[m][1], ah[m][2], ah[m][3],
                         bl[nn][1], bl[nn][3]);
                mma16816(c0[0], c0[1], c0[2], c0[3],
                         al[m][0], al[m][1], al[m][2], al[m][3],
                         bh[nn][0], bh[nn][2]);
                mma16816(c1[0], c1[1], c1[2], c1[3],
                         al[m][0], al[m][1], al[m][2], al[m][3],
                         bh[nn][1], bh[nn][3]);
            }
        }
    }

    const int gq = lane >> 2, tq = lane & 3;
#pragma unroll
    for (int nf = 0; nf < 4; ++nf) {
        int col = bn * 64 + nc2 * 32 + nf * 8 + tq * 2;
        float2 bb = *(const float2*)(bih + col);
#pragma unroll
        for (int m = 0; m < 2; ++m) {
            int row = bm * 128 + mr2 * 32 + m * 16 + gq;
            float2 o0 = make_float2(c[m][nf][0] + bb.x, c[m][nf][1] + bb.y);
            float2 o1 = make_float2(c[m][nf][2] + bb.x, c[m][nf][3] + bb.y);
            *(float2*)(g_xg + (size_t)row * GG + col) = o0;
            *(float2*)(g_xg + (size_t)(row + 8) * GG + col) = o1;
        }
    }
}

// ---------------------------------------------------------------------------
// Phase 2: R8-structure HMMA recurrence + k-PERMUTED own-slice overlap.
// Slot k' holds physical k = (k' + (s+1)*64) mod 256, so this CTA's own
// 64 h-values live at slots 192-255 (written by LOCAL STS during gates).
// Per step: own-k GEMM (kt 12-15, no wait) -> mbar wait -> peer GEMM
// (kt 0-11) -> ps/gates -> local STS + 3 remote pushes -> arrive -> out STG.
// ---------------------------------------------------------------------------
#define TPB2 384

#define OFF_W2   0                        // 12*16*32*16 = 98304
#define OFF_HSM  98304                    // 2*256*32 = 16384
#define OFF_PS   114688                   // 192*8*4  = 6144
#define OFF_BSM  120832                   // 768
#define OFF_MBAR 121600                   // 8
#define SM2_BYTES 121664

__device__ __forceinline__ void mbar_waitc(uint32_t mbar, uint32_t parity) {
    uint32_t done;
    asm volatile(
        "{\n\t.reg .pred p;\n\t"
        "mbarrier.try_wait.parity.acquire.cluster.shared::cta.b64 p, [%1], %2;\n\t"
        "selp.b32 %0, 1, 0, p;\n\t}"
        : "=r"(done) : "r"(mbar), "r"(parity) : "memory");
    if (!done) {
        asm volatile(
            "{\n\t.reg .pred P1;\n\t"
            "W%=:\n\t"
            "mbarrier.try_wait.parity.acquire.cluster.shared::cta.b64 P1, [%0], %1, 0x989680;\n\t"
            "@P1 bra.uni D%=;\n\t"
            "bra.uni W%=;\n\t"
            "D%=:\n\t}"
            :: "r"(mbar), "r"(parity) : "memory");
    }
}

__global__ __launch_bounds__(TPB2, 1) __cluster_dims__(4, 1, 1)
void gru_seq_mma(const float* __restrict__ Whh,
                 const float* __restrict__ bhh,
                 float* __restrict__ out)
{
    extern __shared__ char smem[];
    const uint32_t smb = (uint32_t)__cvta_generic_to_shared(smem);
    float* ps  = (float*)(smem + OFF_PS);
    float* bsm = (float*)(smem + OFF_BSM);

    const int tid  = threadIdx.x;
    const int wid  = tid >> 5;
    const int lane = tid & 31;
    const int gq   = lane >> 2;
    const int tq   = lane & 3;
    uint32_t srank;
    asm("mov.u32 %0, %%cluster_ctarank;" : "=r"(srank));
    const int s = (int)srank;
    const int g = blockIdx.x >> 2;
    const int kperm = ((s + 1) << 6);     // physical-k offset for slot 0

    // ---- init: W1 frags -> regs, W2 frags -> SMEM (permuted columns) ----
    uint32_t w1f[16][4];
    {
        const int r0g = ((wid * 16 + gq) >> 6 << 8) + (s << 6) + ((wid * 16 + gq) & 63);
        const int r1g = ((wid * 16 + gq + 8) >> 6 << 8) + (s << 6) + ((wid * 16 + gq + 8) & 63);
        const float* W0 = Whh + (size_t)r0g * 256;
        const float* W1 = Whh + (size_t)r1g * 256;
#pragma unroll
        for (int kt = 0; kt < 16; ++kt) {
            int c0 = (kt * 16 + tq * 2 + kperm) & 255;   // physical col
            float w00 = W0[c0],     w01 = W0[c0 + 1];
            float w10 = W1[c0],     w11 = W1[c0 + 1];
            float w02 = W0[c0 + 8], w03 = W0[c0 + 9];
            float w12 = W1[c0 + 8], w13 = W1[c0 + 9];
            w1f[kt][0] = pkbf(w00, w01);
            w1f[kt][1] = pkbf(w10, w11);
            w1f[kt][2] = pkbf(w02, w03);
            w1f[kt][3] = pkbf(w12, w13);
            uint4 w2;
            w2.x = pkbf(bfres(w00), bfres(w01));
            w2.y = pkbf(bfres(w10), bfres(w11));
            w2.z = pkbf(bfres(w02), bfres(w03));
            w2.w = pkbf(bfres(w12), bfres(w13));
            *(uint4*)(smem + OFF_W2 + (((wid * 16 + kt) * 32) + lane) * 16) = w2;
        }
    }
    if (tid < 192) {
        int grow = ((tid >> 6) << 8) + (s << 6) + (tid & 63);
        bsm[tid] = bhh[grow];
    }
    for (int i = tid; i < 16384 / 4; i += TPB2)
        ((float*)(smem + OFF_HSM))[i] = 0.f;
    if (tid == 0) {
        asm volatile("mbarrier.init.shared.b64 [%0], %1;"
                     :: "r"(smb + OFF_MBAR), "r"(4u) : "memory");
    }
    __syncthreads();
    asm volatile("barrier.cluster.arrive.aligned;" ::: "memory");
    asm volatile("barrier.cluster.wait.aligned;" ::: "memory");

    const int jj = tid >> 2;              // gate j (tid<256)
    const int bq = (tid & 3) * 2;         // gate batch pair
    const int kln = lane & 15;

    float br = 0.f, bz = 0.f, bn_ = 0.f;
    if (tid < 256) { br = bsm[jj]; bz = bsm[64 + jj]; bn_ = bsm[128 + jj]; }

    // push address (slot = c*64 + jj; swizzle bit = (jj>>2)&1, rank-indep)
    const uint32_t pushbase = (uint32_t)(OFF_HSM + jj * 32 + (((jj >> 2) & 1) << 4) + bq * 2);

    const char* w2p = smem + OFF_W2 + (size_t)wid * 8192 + lane * 16;

    float2 ho = make_float2(0.f, 0.f);

    for (int t = 0; t < TT; ++t) {
        const int p = t & 1;
        const uint32_t hbase = smb + (uint32_t)(OFF_HSM + p * 8192);

        // prefetch xg(t)
        float xr0, xz0, xn0, xr1, xz1, xn1;
        if (tid < 256) {
            size_t base = ((size_t)(g * 8 + bq) * TT + t) * GG + (s << 6) + jj;
            xr0 = g_xg[base];          xz0 = g_xg[base + 256];
            xn0 = g_xg[base + 512];
            xr1 = g_xg[base + (size_t)TT * GG];
            xz1 = g_xg[base + (size_t)TT * GG + 256];
            xn1 = g_xg[base + (size_t)TT * GG + 512];
        }

        float c0 = 0.f, c1 = 0.f, c2 = 0.f, c3 = 0.f;

        // ---- GEMM-A: OWN slots (kt 12..15) — local data, no wait ----
#pragma unroll
        for (int kt = 12; kt < 16; ++kt) {
            int k0 = kt * 16 + kln;
            uint32_t rowHi = hbase + (uint32_t)(k0 * 32 + (((k0 >> 2) & 1) << 4));
            uint32_t rowLo = rowHi ^ 16u;
            uint32_t bh0, bh1, bl0, bl1;
            ldsm_x2t(bh0, bh1, rowHi);
            ldsm_x2t(bl0, bl1, rowLo);
            uint4 w2 = *(const uint4*)(w2p + kt * 512);
            mma16816(c0, c1, c2, c3,
                     w1f[kt][0], w1f[kt][1], w1f[kt][2], w1f[kt][3], bh0, bh1);
            mma16816(c0, c1, c2, c3,
                     w1f[kt][0], w1f[kt][1], w1f[kt][2], w1f[kt][3], bl0, bl1);
            mma16816(c0, c1, c2, c3, w2.x, w2.y, w2.z, w2.w, bh0, bh1);
        }

        // ---- wait for peers' step t-1 pushes ----
        if (t) mbar_waitc(smb + OFF_MBAR, (uint32_t)((t - 1) & 1));

        // ---- GEMM-B: peer slots (kt 0..11) ----
#pragma unroll
        for (int kt = 0; kt < 12; ++kt) {
            int k0 = kt * 16 + kln;
            uint32_t rowHi = hbase + (uint32_t)(k0 * 32 + (((k0 >> 2) & 1) << 4));
            uint32_t rowLo = rowHi ^ 16u;
            uint32_t bh0, bh1, bl0, bl1;
            ldsm_x2t(bh0, bh1, rowHi);
            ldsm_x2t(bl0, bl1, rowLo);
            uint4 w2 = *(const uint4*)(w2p + kt * 512);
            mma16816(c0, c1, c2, c3,
                     w1f[kt][0], w1f[kt][1], w1f[kt][2], w1f[kt][3], bh0, bh1);
            mma16816(c0, c1, c2, c3,
                     w1f[kt][0], w1f[kt][1], w1f[kt][2], w1f[kt][3], bl0, bl1);
            mma16816(c0, c1, c2, c3, w2.x, w2.y, w2.z, w2.w, bh0, bh1);
        }

        *(float2*)(ps + (wid * 16 + gq) * 8 + tq * 2)     = make_float2(c0, c1);
        *(float2*)(ps + (wid * 16 + gq + 8) * 8 + tq * 2) = make_float2(c2, c3);
        __syncthreads();

        // ---- gates ----
        float hw0 = 0.f, hw1 = 0.f;
        if (tid < 256) {
            float2 hr = *(const float2*)(ps + jj * 8 + bq);
            float2 hz = *(const float2*)(ps + (64 + jj) * 8 + bq);
            float2 hn = *(const float2*)(ps + (128 + jj) * 8 + bq);

            float r0g = __fdividef(1.f, 1.f + __expf(-(xr0 + hr.x + br)));
            float z0g = __fdividef(1.f, 1.f + __expf(-(xz0 + hz.x + bz)));
            float v0  = xn0 + r0g * (hn.x + bn_);
            float n0  = 1.f - 2.f * __fdividef(1.f, __expf(2.f * v0) + 1.f);
            hw0 = (1.f - z0g) * n0 + z0g * ho.x;

            float r1g = __fdividef(1.f, 1.f + __expf(-(xr1 + hr.y + br)));
            float z1g = __fdividef(1.f, 1.f + __expf(-(xz1 + hz.y + bz)));
            float v1  = xn1 + r1g * (hn.y + bn_);
            float n1  = 1.f - 2.f * __fdividef(1.f, __expf(2.f * v1) + 1.f);
            hw1 = (1.f - z1g) * n1 + z1g * ho.y;

            uint32_t hiw = pkbf(hw0, hw1);
            uint32_t low = pkbf(bfres(hw0), bfres(hw1));

            uint32_t base = smb + pushbase + (uint32_t)((1 - p) * 8192);
            // local store at own slot (c = 3 -> +3*2048)
            asm volatile("st.shared.b32 [%0], %1;"
                         :: "r"(base + 6144u), "r"(hiw) : "memory");
            asm volatile("st.shared.b32 [%0], %1;"
                         :: "r"((base + 6144u) ^ 16u), "r"(low) : "memory");
            // remote pushes to 3 peers at their permuted slots
#pragma unroll
            for (int rk = 0; rk < 4; ++rk) {
                if (rk == s) continue;
                uint32_t cslot = (uint32_t)(((s - rk - 1) & 3) << 11);  // c*2048
                uint32_t ra, rb;
                asm volatile("mapa.shared::cluster.u32 %0, %1, %2;"
                             : "=r"(ra) : "r"(base + cslot), "r"(rk));
                asm volatile("mapa.shared::cluster.u32 %0, %1, %2;"
                             : "=r"(rb) : "r"((base + cslot) ^ 16u), "r"(rk));
                asm volatile("st.shared::cluster.b32 [%0], %1;"
                             :: "r"(ra), "r"(hiw) : "memory");
                asm volatile("st.shared::cluster.b32 [%0], %1;"
                             :: "r"(rb), "r"(low) : "memory");
            }
            ho = make_float2(hw0, hw1);
        }
        __syncthreads();

        // ---- signal all ranks, THEN write outputs ----
        if (tid == 0) {
            asm volatile("fence.acq_rel.cluster;" ::: "memory");
#pragma unroll
            for (int rk = 0; rk < 4; ++rk) {
                uint32_t ra;
                asm volatile("mapa.shared::cluster.u32 %0, %1, %2;"
                             : "=r"(ra) : "r"(smb + OFF_MBAR), "r"(rk));
                asm volatile("mbarrier.arrive.shared::cluster.b64 _, [%0];"
                             :: "r"(ra) : "memory");
            }
        }
        if (tid < 256) {
            size_t ob = ((size_t)(g * 8 + bq) * TT + t) * HH + (s << 6) + jj;
            out[ob] = hw0;
            out[ob + (size_t)TT * HH] = hw1;
        }
    }

    asm volatile("barrier.cluster.arrive.aligned;" ::: "memory");
    asm volatile("barrier.cluster.wait.aligned;" ::: "memory");
}

// ---------------------------------------------------------------------------
extern "C" void kernel_launch(void* const* d_in, const int* in_sizes, int n_in,
                              void* d_out, int out_size)
{
    const float* x   = (const float*)d_in[0];
    const float* Wih = (const float*)d_in[1];
    const float* Whh = (const float*)d_in[2];
    const float* bih = (const float*)d_in[3];
    const float* bhh = (const float*)d_in[4];
    float* out = (float*)d_out;

    cudaFuncSetAttribute(xg_mma_kernel,
                         cudaFuncAttributeMaxDynamicSharedMemorySize, SM1_BYTES);
    cudaFuncSetAttribute(gru_seq_mma,
                         cudaFuncAttributeMaxDynamicSharedMemorySize, SM2_BYTES);

    dim3 g1(GG / 64, BB * TT / 128);
    xg_mma_kernel<<<g1, 256, SM1_BYTES>>>(x, Wih, bih);
    gru_seq_mma<<<128, TPB2, SM2_BYTES>>>(Whh, bhh, out);
}

// round 13
// speedup vs baseline: 1.3617x; 1.0286x over previous
#include <cuda_runtime.h>
#include <cuda_bf16.h>
#include <cstdint>
#include <cstddef>

#define BB 256
#define TT 512
#define II 128
#define HH 256
#define GG 768

typedef unsigned long long u64;

__device__ float g_xg[(size_t)BB * TT * GG];

// ---------------- bf16 helpers ----------------
__device__ __forceinline__ uint32_t pkbf(float x, float y) {
    __nv_bfloat162 h = __floats2bfloat162_rn(x, y);
    return *(uint32_t*)&h;
}
__device__ __forceinline__ float bfres(float x) {   // x - bf16(x)
    return x - __bfloat162float(__float2bfloat16(x));
}
__device__ __forceinline__ void ldsm_x4(uint32_t& r0, uint32_t& r1,
                                        uint32_t& r2, uint32_t& r3, uint32_t a) {
    asm volatile("ldmatrix.sync.aligned.m8n8.x4.shared.b16 {%0,%1,%2,%3}, [%4];"
                 : "=r"(r0), "=r"(r1), "=r"(r2), "=r"(r3) : "r"(a));
}
__device__ __forceinline__ void ldsm_x2t(uint32_t& r0, uint32_t& r1, uint32_t a) {
    asm volatile("ldmatrix.sync.aligned.m8n8.x2.trans.shared.b16 {%0,%1}, [%2];"
                 : "=r"(r0), "=r"(r1) : "r"(a));
}
__device__ __forceinline__ void mma16816(float& c0, float& c1, float& c2, float& c3,
                                         uint32_t a0, uint32_t a1, uint32_t a2, uint32_t a3,
                                         uint32_t b0, uint32_t b1) {
    asm("mma.sync.aligned.m16n8k16.row.col.f32.bf16.bf16.f32 "
        "{%0,%1,%2,%3}, {%4,%5,%6,%7}, {%8,%9}, {%0,%1,%2,%3};"
        : "+f"(c0), "+f"(c1), "+f"(c2), "+f"(c3)
        : "r"(a0), "r"(a1), "r"(a2), "r"(a3), "r"(b0), "r"(b1));
}

// ---------------------------------------------------------------------------
// Phase 1 (frozen, ~284us): xg = x @ W_ih^T + b_ih, HMMA bf16-split.
// ---------------------------------------------------------------------------
#define SM1_AHI 0
#define SM1_ALO 32768
#define SM1_BHI 65536
#define SM1_BLO 81920
#define SM1_BYTES 98304

__global__ __launch_bounds__(256, 2) void xg_mma_kernel(
    const float* __restrict__ x,
    const float* __restrict__ Wih,
    const float* __restrict__ bih)
{
    extern __shared__ char sm1[];
    const uint32_t smb = (uint32_t)__cvta_generic_to_shared(sm1);
    const int tid  = threadIdx.x;
    const int warp = tid >> 5;
    const int lane = tid & 31;
    const int bn = blockIdx.x;
    const int bm = blockIdx.y;

    {
        const float* xr = x + (size_t)bm * 128 * II;
        const int r_ = tid >> 5, kq = tid & 31;
        const uint32_t off0 = (uint32_t)((((kq >> 1) ^ (r_ & 7)) << 4) + (kq & 1) * 8);
#pragma unroll
        for (int i = 0; i < 16; ++i) {
            int r = r_ + i * 8;
            float4 v = *(const float4*)(xr + (size_t)r * II + kq * 4);
            uint2 hi = make_uint2(pkbf(v.x, v.y), pkbf(v.z, v.w));
            uint2 lo = make_uint2(pkbf(bfres(v.x), bfres(v.y)),
                                  pkbf(bfres(v.z), bfres(v.w)));
            uint32_t off = (uint32_t)(r * 256) + off0;
            *(uint2*)(sm1 + SM1_AHI + off) = hi;
            *(uint2*)(sm1 + SM1_ALO + off) = lo;
        }
        const float* wr = Wih + (size_t)bn * 64 * II;
#pragma unroll
        for (int i = 0; i < 8; ++i) {
            int n = r_ + i * 8;
            float4 v = *(const float4*)(wr + (size_t)n * II + kq * 4);
            uint2 hi = make_uint2(pkbf(v.x, v.y), pkbf(v.z, v.w));
            uint2 lo = make_uint2(pkbf(bfres(v.x), bfres(v.y)),
                                  pkbf(bfres(v.z), bfres(v.w)));
            uint32_t off = (uint32_t)(n * 256) + off0;
            *(uint2*)(sm1 + SM1_BHI + off) = hi;
            *(uint2*)(sm1 + SM1_BLO + off) = lo;
        }
    }
    __syncthreads();

    const int mr2 = warp >> 1;
    const int nc2 = warp & 1;
    const uint32_t lrow  = (uint32_t)(lane & 15);
    const uint32_t khalf = (uint32_t)(lane >> 4);
    const uint32_t r7    = lrow & 7u;
    const uint32_t aRB = smb + SM1_AHI + (uint32_t)(mr2 * 32 + lrow) * 256u;
    const uint32_t bRB = smb + SM1_BHI + (uint32_t)(nc2 * 32 + lrow) * 256u;

    float c[2][4][4];
#pragma unroll
    for (int m = 0; m < 2; ++m)
#pragma unroll
        for (int n = 0; n < 4; ++n)
#pragma unroll
            for (int q = 0; q < 4; ++q) c[m][n][q] = 0.f;

#pragma unroll
    for (int kt = 0; kt < 8; ++kt) {
        const uint32_t swz = (((uint32_t)(kt * 2) + khalf) ^ r7) << 4;
        uint32_t ah[2][4], al[2][4], bh[2][4], bl[2][4];
#pragma unroll
        for (int m = 0; m < 2; ++m) {
            uint32_t a = aRB + (uint32_t)(m * 4096) + swz;
            ldsm_x4(ah[m][0], ah[m][1], ah[m][2], ah[m][3], a);
            ldsm_x4(al[m][0], al[m][1], al[m][2], al[m][3], a + 32768u);
        }
#pragma unroll
        for (int nn = 0; nn < 2; ++nn) {
            uint32_t b = bRB + (uint32_t)(nn * 4096) + swz;
            ldsm_x4(bh[nn][0], bh[nn][1], bh[nn][2], bh[nn][3], b);
            ldsm_x4(bl[nn][0], bl[nn][1], bl[nn][2], bl[nn][3], b + 16384u);
        }
#pragma unroll
        for (int m = 0; m < 2; ++m) {
#pragma unroll
            for (int nn = 0; nn < 2; ++nn) {
                float* c0 = c[m][nn * 2];
                float* c1 = c[m][nn * 2 + 1];
                mma16816(c0[0], c0[1], c0[2], c0[3],
                         ah[m][0], ah[m][1], ah[m][2], ah[m][3],
                         bh[nn][0], bh[nn][2]);
                mma16816(c1[0], c1[1], c1[2], c1[3],
                         ah[m][0], ah[m][1], ah[m][2], ah[m][3],
                         bh[nn][1], bh[nn][3]);
                mma16816(c0[0], c0[1], c0[2], c0[3],
                         ah[m][0], ah[m][1], ah[m][2], ah[m][3],
                         bl[nn][0], bl[nn][2]);
                mma16816(c1[0], c1[1], c1[2], c1[3],
                         ah[m][0], ah[m][1], ah[m][2], ah[m][3],
                         bl[nn][1], bl[nn][3]);
                mma16816(c0[0], c0[1], c0[2], c0[3],
                         al[m][0], al[m][1], al[m][2], al[m][3],
                         bh[nn][0], bh[nn][2]);
                mma16816(c1[0], c1[1], c1[2], c1[3],
                         al[m][0], al[m][1], al[m][2], al[m][3],
                         bh[nn][1], bh[nn][3]);
            }
        }
    }

    const int gq = lane >> 2, tq = lane & 3;
#pragma unroll
    for (int nf = 0; nf < 4; ++nf) {
        int col = bn * 64 + nc2 * 32 + nf * 8 + tq * 2;
        float2 bb = *(const float2*)(bih + col);
#pragma unroll
        for (int m = 0; m < 2; ++m) {
            int row = bm * 128 + mr2 * 32 + m * 16 + gq;
            float2 o0 = make_float2(c[m][nf][0] + bb.x, c[m][nf][1] + bb.y);
            float2 o1 = make_float2(c[m][nf][2] + bb.x, c[m][nf][3] + bb.y);
            *(float2*)(g_xg + (size_t)row * GG + col) = o0;
            *(float2*)(g_xg + (size_t)(row + 8) * GG + col) = o1;
        }
    }
}

// ---------------------------------------------------------------------------
// Phase 2: R12 structure (k-permuted own-slice overlap) + DUAL accumulator
// chains by kt parity (breaks the 48-MMA serialized RAW chain into 2x24).
// ---------------------------------------------------------------------------
#define TPB2 384

#define OFF_W2   0                        // 12*16*32*16 = 98304
#define OFF_HSM  98304                    // 2*256*32 = 16384
#define OFF_PS   114688                   // 192*8*4  = 6144
#define OFF_BSM  120832                   // 768
#define OFF_MBAR 121600                   // 8
#define SM2_BYTES 121664

__device__ __forceinline__ void mbar_waitc(uint32_t mbar, uint32_t parity) {
    uint32_t done;
    asm volatile(
        "{\n\t.reg .pred p;\n\t"
        "mbarrier.try_wait.parity.acquire.cluster.shared::cta.b64 p, [%1], %2;\n\t"
        "selp.b32 %0, 1, 0, p;\n\t}"
        : "=r"(done) : "r"(mbar), "r"(parity) : "memory");
    if (!done) {
        asm volatile(
            "{\n\t.reg .pred P1;\n\t"
            "W%=:\n\t"
            "mbarrier.try_wait.parity.acquire.cluster.shared::cta.b64 P1, [%0], %1, 0x989680;\n\t"
            "@P1 bra.uni D%=;\n\t"
            "bra.uni W%=;\n\t"
            "D%=:\n\t}"
            :: "r"(mbar), "r"(parity) : "memory");
    }
}

__global__ __launch_bounds__(TPB2, 1) __cluster_dims__(4, 1, 1)
void gru_seq_mma(const float* __restrict__ Whh,
                 const float* __restrict__ bhh,
                 float* __restrict__ out)
{
    extern __shared__ char smem[];
    const uint32_t smb = (uint32_t)__cvta_generic_to_shared(smem);
    float* ps  = (float*)(smem + OFF_PS);
    float* bsm = (float*)(smem + OFF_BSM);

    const int tid  = threadIdx.x;
    const int wid  = tid >> 5;
    const int lane = tid & 31;
    const int gq   = lane >> 2;
    const int tq   = lane & 3;
    uint32_t srank;
    asm("mov.u32 %0, %%cluster_ctarank;" : "=r"(srank));
    const int s = (int)srank;
    const int g = blockIdx.x >> 2;
    const int kperm = ((s + 1) << 6);     // physical-k offset for slot 0

    // ---- init: W1 frags -> regs, W2 frags -> SMEM (permuted columns) ----
    uint32_t w1f[16][4];
    {
        const int r0g = ((wid * 16 + gq) >> 6 << 8) + (s << 6) + ((wid * 16 + gq) & 63);
        const int r1g = ((wid * 16 + gq + 8) >> 6 << 8) + (s << 6) + ((wid * 16 + gq + 8) & 63);
        const float* W0 = Whh + (size_t)r0g * 256;
        const float* W1 = Whh + (size_t)r1g * 256;
#pragma unroll
        for (int kt = 0; kt < 16; ++kt) {
            int c0 = (kt * 16 + tq * 2 + kperm) & 255;   // physical col
            float w00 = W0[c0],     w01 = W0[c0 + 1];
            float w10 = W1[c0],     w11 = W1[c0 + 1];
            float w02 = W0[c0 + 8], w03 = W0[c0 + 9];
            float w12 = W1[c0 + 8], w13 = W1[c0 + 9];
            w1f[kt][0] = pkbf(w00, w01);
            w1f[kt][1] = pkbf(w10, w11);
            w1f[kt][2] = pkbf(w02, w03);
            w1f[kt][3] = pkbf(w12, w13);
            uint4 w2;
            w2.x = pkbf(bfres(w00), bfres(w01));
            w2.y = pkbf(bfres(w10), bfres(w11));
            w2.z = pkbf(bfres(w02), bfres(w03));
            w2.w = pkbf(bfres(w12), bfres(w13));
            *(uint4*)(smem + OFF_W2 + (((wid * 16 + kt) * 32) + lane) * 16) = w2;
        }
    }
    if (tid < 192) {
        int grow = ((tid >> 6) << 8) + (s << 6) + (tid & 63);
        bsm[tid] = bhh[grow];
    }
    for (int i = tid; i < 16384 / 4; i += TPB2)
        ((float*)(smem + OFF_HSM))[i] = 0.f;
    if (tid == 0) {
        asm volatile("mbarrier.init.shared.b64 [%0], %1;"
                     :: "r"(smb + OFF_MBAR), "r"(4u) : "memory");
    }
    __syncthreads();
    asm volatile("barrier.cluster.arrive.aligned;" ::: "memory");
    asm volatile("barrier.cluster.wait.aligned;" ::: "memory");

    const int jj = tid >> 2;              // gate j (tid<256)
    const int bq = (tid & 3) * 2;         // gate batch pair
    const int kln = lane & 15;

    float br = 0.f, bz = 0.f, bn_ = 0.f;
    if (tid < 256) { br = bsm[jj]; bz = bsm[64 + jj]; bn_ = bsm[128 + jj]; }

    const uint32_t pushbase = (uint32_t)(OFF_HSM + jj * 32 + (((jj >> 2) & 1) << 4) + bq * 2);

    const char* w2p = smem + OFF_W2 + (size_t)wid * 8192 + lane * 16;

    float2 ho = make_float2(0.f, 0.f);

    for (int t = 0; t < TT; ++t) {
        const int p = t & 1;
        const uint32_t hbase = smb + (uint32_t)(OFF_HSM + p * 8192);

        // prefetch xg(t)
        float xr0, xz0, xn0, xr1, xz1, xn1;
        if (tid < 256) {
            size_t base = ((size_t)(g * 8 + bq) * TT + t) * GG + (s << 6) + jj;
            xr0 = g_xg[base];          xz0 = g_xg[base + 256];
            xn0 = g_xg[base + 512];
            xr1 = g_xg[base + (size_t)TT * GG];
            xz1 = g_xg[base + (size_t)TT * GG + 256];
            xn1 = g_xg[base + (size_t)TT * GG + 512];
        }

        // two independent accumulator chains (kt parity)
        float e0 = 0.f, e1 = 0.f, e2 = 0.f, e3 = 0.f;   // even kt
        float o0 = 0.f, o1 = 0.f, o2 = 0.f, o3 = 0.f;   // odd kt

        // ---- GEMM-A: OWN slots (kt 12..15) — local data, no wait ----
#pragma unroll
        for (int kt = 12; kt < 16; ++kt) {
            int k0 = kt * 16 + kln;
            uint32_t rowHi = hbase + (uint32_t)(k0 * 32 + (((k0 >> 2) & 1) << 4));
            uint32_t rowLo = rowHi ^ 16u;
            uint32_t bh0, bh1, bl0, bl1;
            ldsm_x2t(bh0, bh1, rowHi);
            ldsm_x2t(bl0, bl1, rowLo);
            uint4 w2 = *(const uint4*)(w2p + kt * 512);
            if (kt & 1) {
                mma16816(o0, o1, o2, o3,
                         w1f[kt][0], w1f[kt][1], w1f[kt][2], w1f[kt][3], bh0, bh1);
                mma16816(o0, o1, o2, o3,
                         w1f[kt][0], w1f[kt][1], w1f[kt][2], w1f[kt][3], bl0, bl1);
                mma16816(o0, o1, o2, o3, w2.x, w2.y, w2.z, w2.w, bh0, bh1);
            } else {
                mma16816(e0, e1, e2, e3,
                         w1f[kt][0], w1f[kt][1], w1f[kt][2], w1f[kt][3], bh0, bh1);
                mma16816(e0, e1, e2, e3,
                         w1f[kt][0], w1f[kt][1], w1f[kt][2], w1f[kt][3], bl0, bl1);
                mma16816(e0, e1, e2, e3, w2.x, w2.y, w2.z, w2.w, bh0, bh1);
            }
        }

        // ---- wait for peers' step t-1 pushes ----
        if (t) mbar_waitc(smb + OFF_MBAR, (uint32_t)((t - 1) & 1));

        // ---- GEMM-B: peer slots (kt 0..11) ----
#pragma unroll
        for (int kt = 0; kt < 12; ++kt) {
            int k0 = kt * 16 + kln;
            uint32_t rowHi = hbase + (uint32_t)(k0 * 32 + (((k0 >> 2) & 1) << 4));
            uint32_t rowLo = rowHi ^ 16u;
            uint32_t bh0, bh1, bl0, bl1;
            ldsm_x2t(bh0, bh1, rowHi);
            ldsm_x2t(bl0, bl1, rowLo);
            uint4 w2 = *(const uint4*)(w2p + kt * 512);
            if (kt & 1) {
                mma16816(o0, o1, o2, o3,
                         w1f[kt][0], w1f[kt][1], w1f[kt][2], w1f[kt][3], bh0, bh1);
                mma16816(o0, o1, o2, o3,
                         w1f[kt][0], w1f[kt][1], w1f[kt][2], w1f[kt][3], bl0, bl1);
                mma16816(o0, o1, o2, o3, w2.x, w2.y, w2.z, w2.w, bh0, bh1);
            } else {
                mma16816(e0, e1, e2, e3,
                         w1f[kt][0], w1f[kt][1], w1f[kt][2], w1f[kt][3], bh0, bh1);
                mma16816(e0, e1, e2, e3,
                         w1f[kt][0], w1f[kt][1], w1f[kt][2], w1f[kt][3], bl0, bl1);
                mma16816(e0, e1, e2, e3, w2.x, w2.y, w2.z, w2.w, bh0, bh1);
            }
        }

        *(float2*)(ps + (wid * 16 + gq) * 8 + tq * 2)     = make_float2(e0 + o0, e1 + o1);
        *(float2*)(ps + (wid * 16 + gq + 8) * 8 + tq * 2) = make_float2(e2 + o2, e3 + o3);
        __syncthreads();

        // ---- gates ----
        float hw0 = 0.f, hw1 = 0.f;
        if (tid < 256) {
            float2 hr = *(const float2*)(ps + jj * 8 + bq);
            float2 hz = *(const float2*)(ps + (64 + jj) * 8 + bq);
            float2 hn = *(const float2*)(ps + (128 + jj) * 8 + bq);

            float r0g = __fdividef(1.f, 1.f + __expf(-(xr0 + hr.x + br)));
            float z0g = __fdividef(1.f, 1.f + __expf(-(xz0 + hz.x + bz)));
            float v0  = xn0 + r0g * (hn.x + bn_);
            float n0  = 1.f - 2.f * __fdividef(1.f, __expf(2.f * v0) + 1.f);
            hw0 = (1.f - z0g) * n0 + z0g * ho.x;

            float r1g = __fdividef(1.f, 1.f + __expf(-(xr1 + hr.y + br)));
            float z1g = __fdividef(1.f, 1.f + __expf(-(xz1 + hz.y + bz)));
            float v1  = xn1 + r1g * (hn.y + bn_);
            float n1  = 1.f - 2.f * __fdividef(1.f, __expf(2.f * v1) + 1.f);
            hw1 = (1.f - z1g) * n1 + z1g * ho.y;

            uint32_t hiw = pkbf(hw0, hw1);
            uint32_t low = pkbf(bfres(hw0), bfres(hw1));

            uint32_t base = smb + pushbase + (uint32_t)((1 - p) * 8192);
            // local store at own slot (c = 3 -> +3*2048)
            asm volatile("st.shared.b32 [%0], %1;"
                         :: "r"(base + 6144u), "r"(hiw) : "memory");
            asm volatile("st.shared.b32 [%0], %1;"
                         :: "r"((base + 6144u) ^ 16u), "r"(low) : "memory");
            // remote pushes to 3 peers at their permuted slots
#pragma unroll
            for (int rk = 0; rk < 4; ++rk) {
                if (rk == s) continue;
                uint32_t cslot = (uint32_t)(((s - rk - 1) & 3) << 11);  // c*2048
                uint32_t ra, rb;
                asm volatile("mapa.shared::cluster.u32 %0, %1, %2;"
                             : "=r"(ra) : "r"(base + cslot), "r"(rk));
                asm volatile("mapa.shared::cluster.u32 %0, %1, %2;"
                             : "=r"(rb) : "r"((base + cslot) ^ 16u), "r"(rk));
                asm volatile("st.shared::cluster.b32 [%0], %1;"
                             :: "r"(ra), "r"(hiw) : "memory");
                asm volatile("st.shared::cluster.b32 [%0], %1;"
                             :: "r"(rb), "r"(low) : "memory");
            }
            ho = make_float2(hw0, hw1);
        }
        __syncthreads();

        // ---- signal all ranks, THEN write outputs ----
        if (tid == 0) {
            asm volatile("fence.acq_rel.cluster;" ::: "memory");
#pragma unroll
            for (int rk = 0; rk < 4; ++rk) {
                uint32_t ra;
                asm volatile("mapa.shared::cluster.u32 %0, %1, %2;"
                             : "=r"(ra) : "r"(smb + OFF_MBAR), "r"(rk));
                asm volatile("mbarrier.arrive.shared::cluster.b64 _, [%0];"
                             :: "r"(ra) : "memory");
            }
        }
        if (tid < 256) {
            size_t ob = ((size_t)(g * 8 + bq) * TT + t) * HH + (s << 6) + jj;
            out[ob] = hw0;
            out[ob + (size_t)TT * HH] = hw1;
        }
    }

    asm volatile("barrier.cluster.arrive.aligned;" ::: "memory");
    asm volatile("barrier.cluster.wait.aligned;" ::: "memory");
}

// ---------------------------------------------------------------------------
extern "C" void kernel_launch(void* const* d_in, const int* in_sizes, int n_in,
                              void* d_out, int out_size)
{
    const float* x   = (const float*)d_in[0];
    const float* Wih = (const float*)d_in[1];
    const float* Whh = (const float*)d_in[2];
    const float* bih = (const float*)d_in[3];
    const float* bhh = (const float*)d_in[4];
    float* out = (float*)d_out;

    cudaFuncSetAttribute(xg_mma_kernel,
                         cudaFuncAttributeMaxDynamicSharedMemorySize, SM1_BYTES);
    cudaFuncSetAttribute(gru_seq_mma,
                         cudaFuncAttributeMaxDynamicSharedMemorySize, SM2_BYTES);

    dim3 g1(GG / 64, BB * TT / 128);
    xg_mma_kernel<<<g1, 256, SM1_BYTES>>>(x, Wih, bih);
    gru_seq_mma<<<128, TPB2, SM2_BYTES>>>(Whh, bhh, out);
}

// round 14
// speedup vs baseline: 1.3844x; 1.0167x over previous
#include <cuda_runtime.h>
#include <cuda_bf16.h>
#include <cstdint>
#include <cstddef>

#define BB 256
#define TT 512
#define II 128
#define HH 256
#define GG 768

typedef unsigned long long u64;

__device__ float g_xg[(size_t)BB * TT * GG];

// ---------------- bf16 helpers ----------------
__device__ __forceinline__ uint32_t pkbf(float x, float y) {
    __nv_bfloat162 h = __floats2bfloat162_rn(x, y);
    return *(uint32_t*)&h;
}
__device__ __forceinline__ float bfres(float x) {   // x - bf16(x)
    return x - __bfloat162float(__float2bfloat16(x));
}
__device__ __forceinline__ void ldsm_x4(uint32_t& r0, uint32_t& r1,
                                        uint32_t& r2, uint32_t& r3, uint32_t a) {
    asm volatile("ldmatrix.sync.aligned.m8n8.x4.shared.b16 {%0,%1,%2,%3}, [%4];"
                 : "=r"(r0), "=r"(r1), "=r"(r2), "=r"(r3) : "r"(a));
}
__device__ __forceinline__ void ldsm_x2t(uint32_t& r0, uint32_t& r1, uint32_t a) {
    asm volatile("ldmatrix.sync.aligned.m8n8.x2.trans.shared.b16 {%0,%1}, [%2];"
                 : "=r"(r0), "=r"(r1) : "r"(a));
}
__device__ __forceinline__ void mma16816(float& c0, float& c1, float& c2, float& c3,
                                         uint32_t a0, uint32_t a1, uint32_t a2, uint32_t a3,
                                         uint32_t b0, uint32_t b1) {
    asm("mma.sync.aligned.m16n8k16.row.col.f32.bf16.bf16.f32 "
        "{%0,%1,%2,%3}, {%4,%5,%6,%7}, {%8,%9}, {%0,%1,%2,%3};"
        : "+f"(c0), "+f"(c1), "+f"(c2), "+f"(c3)
        : "r"(a0), "r"(a1), "r"(a2), "r"(a3), "r"(b0), "r"(b1));
}

// ---------------------------------------------------------------------------
// Phase 1 v2 (persistent over bn): xg = x @ W_ih^T + b_ih, HMMA bf16-split.
// Grid = 1024 CTAs (one per 128-row x tile). A staged ONCE; loop over the 12
// N-tiles with next W tile prefetched into registers under current compute.
// ---------------------------------------------------------------------------
#define SM1_AHI 0
#define SM1_ALO 32768
#define SM1_BHI 65536
#define SM1_BLO 81920
#define SM1_BYTES 98304

__global__ __launch_bounds__(256, 2) void xg_mma_kernel(
    const float* __restrict__ x,
    const float* __restrict__ Wih,
    const float* __restrict__ bih)
{
    extern __shared__ char sm1[];
    const uint32_t smb = (uint32_t)__cvta_generic_to_shared(sm1);
    const int tid  = threadIdx.x;
    const int warp = tid >> 5;
    const int lane = tid & 31;
    const int bm = blockIdx.x;          // 0..1023

    const int r_ = tid >> 5, kq = tid & 31;
    const uint32_t off0 = (uint32_t)((((kq >> 1) ^ (r_ & 7)) << 4) + (kq & 1) * 8);

    // ---- stage A once (x tile 128x128 fp32 -> bf16 hi/lo, swizzled) ----
    {
        const float* xr = x + (size_t)bm * 128 * II;
#pragma unroll
        for (int i = 0; i < 16; ++i) {
            int r = r_ + i * 8;
            float4 v = *(const float4*)(xr + (size_t)r * II + kq * 4);
            uint2 hi = make_uint2(pkbf(v.x, v.y), pkbf(v.z, v.w));
            uint2 lo = make_uint2(pkbf(bfres(v.x), bfres(v.y)),
                                  pkbf(bfres(v.z), bfres(v.w)));
            uint32_t off = (uint32_t)(r * 256) + off0;
            *(uint2*)(sm1 + SM1_AHI + off) = hi;
            *(uint2*)(sm1 + SM1_ALO + off) = lo;
        }
    }

    // ---- prefetch W tile for bn = 0 into registers ----
    float4 wv[8];
#pragma unroll
    for (int i = 0; i < 8; ++i) {
        int n = r_ + i * 8;
        wv[i] = *(const float4*)(Wih + (size_t)n * II + kq * 4);
    }

    const int mr2 = warp >> 1;
    const int nc2 = warp & 1;
    const uint32_t lrow  = (uint32_t)(lane & 15);
    const uint32_t khalf = (uint32_t)(lane >> 4);
    const uint32_t r7    = lrow & 7u;
    const uint32_t aRB = smb + SM1_AHI + (uint32_t)(mr2 * 32 + lrow) * 256u;
    const uint32_t bRB = smb + SM1_BHI + (uint32_t)(nc2 * 32 + lrow) * 256u;
    const int gq = lane >> 2, tq = lane & 3;

    for (int bn = 0; bn < 12; ++bn) {
        if (bn) __syncthreads();        // all warps done reading prior B tile

        // ---- store W regs -> B smem (bf16 hi/lo, swizzled) ----
#pragma unroll
        for (int i = 0; i < 8; ++i) {
            int n = r_ + i * 8;
            float4 v = wv[i];
            uint2 hi = make_uint2(pkbf(v.x, v.y), pkbf(v.z, v.w));
            uint2 lo = make_uint2(pkbf(bfres(v.x), bfres(v.y)),
                                  pkbf(bfres(v.z), bfres(v.w)));
            uint32_t off = (uint32_t)(n * 256) + off0;
            *(uint2*)(sm1 + SM1_BHI + off) = hi;
            *(uint2*)(sm1 + SM1_BLO + off) = lo;
        }
        __syncthreads();

        // ---- prefetch next W tile (LDG hidden under compute) ----
        if (bn < 11) {
            const float* wr = Wih + (size_t)(bn + 1) * 64 * II;
#pragma unroll
            for (int i = 0; i < 8; ++i) {
                int n = r_ + i * 8;
                wv[i] = *(const float4*)(wr + (size_t)n * II + kq * 4);
            }
        }

        // ---- compute (identical to proven R9 inner loop) ----
        float c[2][4][4];
#pragma unroll
        for (int m = 0; m < 2; ++m)
#pragma unroll
            for (int n = 0; n < 4; ++n)
#pragma unroll
                for (int q = 0; q < 4; ++q) c[m][n][q] = 0.f;

#pragma unroll
        for (int kt = 0; kt < 8; ++kt) {
            const uint32_t swz = (((uint32_t)(kt * 2) + khalf) ^ r7) << 4;
            uint32_t ah[2][4], al[2][4], bh[2][4], bl[2][4];
#pragma unroll
            for (int m = 0; m < 2; ++m) {
                uint32_t a = aRB + (uint32_t)(m * 4096) + swz;
                ldsm_x4(ah[m][0], ah[m][1], ah[m][2], ah[m][3], a);
                ldsm_x4(al[m][0], al[m][1], al[m][2], al[m][3], a + 32768u);
            }
#pragma unroll
            for (int nn = 0; nn < 2; ++nn) {
                uint32_t b = bRB + (uint32_t)(nn * 4096) + swz;
                ldsm_x4(bh[nn][0], bh[nn][1], bh[nn][2], bh[nn][3], b);
                ldsm_x4(bl[nn][0], bl[nn][1], bl[nn][2], bl[nn][3], b + 16384u);
            }
#pragma unroll
            for (int m = 0; m < 2; ++m) {
#pragma unroll
                for (int nn = 0; nn < 2; ++nn) {
                    float* c0 = c[m][nn * 2];
                    float* c1 = c[m][nn * 2 + 1];
                    mma16816(c0[0], c0[1], c0[2], c0[3],
                             ah[m][0], ah[m][1], ah[m][2], ah[m][3],
                             bh[nn][0], bh[nn][2]);
                    mma16816(c1[0], c1[1], c1[2], c1[3],
                             ah[m][0], ah[m][1], ah[m][2], ah[m][3],
                             bh[nn][1], bh[nn][3]);
                    mma16816(c0[0], c0[1], c0[2], c0[3],
                             ah[m][0], ah[m][1], ah[m][2], ah[m][3],
                             bl[nn][0], bl[nn][2]);
                    mma16816(c1[0], c1[1], c1[2], c1[3],
                             ah[m][0], ah[m][1], ah[m][2], ah[m][3],
                             bl[nn][1], bl[nn][3]);
                    mma16816(c0[0], c0[1], c0[2], c0[3],
                             al[m][0], al[m][1], al[m][2], al[m][3],
                             bh[nn][0], bh[nn][2]);
                    mma16816(c1[0], c1[1], c1[2], c1[3],
                             al[m][0], al[m][1], al[m][2], al[m][3],
                             bh[nn][1], bh[nn][3]);
                }
            }
        }

        // ---- epilogue: add bias, store fp32 ----
#pragma unroll
        for (int nf = 0; nf < 4; ++nf) {
            int col = bn * 64 + nc2 * 32 + nf * 8 + tq * 2;
            float2 bb = *(const float2*)(bih + col);
#pragma unroll
            for (int m = 0; m < 2; ++m) {
                int row = bm * 128 + mr2 * 32 + m * 16 + gq;
                float2 o0 = make_float2(c[m][nf][0] + bb.x, c[m][nf][1] + bb.y);
                float2 o1 = make_float2(c[m][nf][2] + bb.x, c[m][nf][3] + bb.y);
                *(float2*)(g_xg + (size_t)row * GG + col) = o0;
                *(float2*)(g_xg + (size_t)(row + 8) * GG + col) = o1;
            }
        }
    }
}

// ---------------------------------------------------------------------------
// Phase 2 (R13, frozen): k-permuted own-slice overlap + dual accumulator
// chains + mbarrier cluster signaling.
// ---------------------------------------------------------------------------
#define TPB2 384

#define OFF_W2   0                        // 12*16*32*16 = 98304
#define OFF_HSM  98304                    // 2*256*32 = 16384
#define OFF_PS   114688                   // 192*8*4  = 6144
#define OFF_BSM  120832                   // 768
#define OFF_MBAR 121600                   // 8
#define SM2_BYTES 121664

__device__ __forceinline__ void mbar_waitc(uint32_t mbar, uint32_t parity) {
    uint32_t done;
    asm volatile(
        "{\n\t.reg .pred p;\n\t"
        "mbarrier.try_wait.parity.acquire.cluster.shared::cta.b64 p, [%1], %2;\n\t"
        "selp.b32 %0, 1, 0, p;\n\t}"
        : "=r"(done) : "r"(mbar), "r"(parity) : "memory");
    if (!done) {
        asm volatile(
            "{\n\t.reg .pred P1;\n\t"
            "W%=:\n\t"
            "mbarrier.try_wait.parity.acquire.cluster.shared::cta.b64 P1, [%0], %1, 0x989680;\n\t"
            "@P1 bra.uni D%=;\n\t"
            "bra.uni W%=;\n\t"
            "D%=:\n\t}"
            :: "r"(mbar), "r"(parity) : "memory");
    }
}

__global__ __launch_bounds__(TPB2, 1) __cluster_dims__(4, 1, 1)
void gru_seq_mma(const float* __restrict__ Whh,
                 const float* __restrict__ bhh,
                 float* __restrict__ out)
{
    extern __shared__ char smem[];
    const uint32_t smb = (uint32_t)__cvta_generic_to_shared(smem);
    float* ps  = (float*)(smem + OFF_PS);
    float* bsm = (float*)(smem + OFF_BSM);

    const int tid  = threadIdx.x;
    const int wid  = tid >> 5;
    const int lane = tid & 31;
    const int gq   = lane >> 2;
    const int tq   = lane & 3;
    uint32_t srank;
    asm("mov.u32 %0, %%cluster_ctarank;" : "=r"(srank));
    const int s = (int)srank;
    const int g = blockIdx.x >> 2;
    const int kperm = ((s + 1) << 6);

    uint32_t w1f[16][4];
    {
        const int r0g = ((wid * 16 + gq) >> 6 << 8) + (s << 6) + ((wid * 16 + gq) & 63);
        const int r1g = ((wid * 16 + gq + 8) >> 6 << 8) + (s << 6) + ((wid * 16 + gq + 8) & 63);
        const float* W0 = Whh + (size_t)r0g * 256;
        const float* W1 = Whh + (size_t)r1g * 256;
#pragma unroll
        for (int kt = 0; kt < 16; ++kt) {
            int c0 = (kt * 16 + tq * 2 + kperm) & 255;
            float w00 = W0[c0],     w01 = W0[c0 + 1];
            float w10 = W1[c0],     w11 = W1[c0 + 1];
            float w02 = W0[c0 + 8], w03 = W0[c0 + 9];
            float w12 = W1[c0 + 8], w13 = W1[c0 + 9];
            w1f[kt][0] = pkbf(w00, w01);
            w1f[kt][1] = pkbf(w10, w11);
            w1f[kt][2] = pkbf(w02, w03);
            w1f[kt][3] = pkbf(w12, w13);
            uint4 w2;
            w2.x = pkbf(bfres(w00), bfres(w01));
            w2.y = pkbf(bfres(w10), bfres(w11));
            w2.z = pkbf(bfres(w02), bfres(w03));
            w2.w = pkbf(bfres(w12), bfres(w13));
            *(uint4*)(smem + OFF_W2 + (((wid * 16 + kt) * 32) + lane) * 16) = w2;
        }
    }
    if (tid < 192) {
        int grow = ((tid >> 6) << 8) + (s << 6) + (tid & 63);
        bsm[tid] = bhh[grow];
    }
    for (int i = tid; i < 16384 / 4; i += TPB2)
        ((float*)(smem + OFF_HSM))[i] = 0.f;
    if (tid == 0) {
        asm volatile("mbarrier.init.shared.b64 [%0], %1;"
                     :: "r"(smb + OFF_MBAR), "r"(4u) : "memory");
    }
    __syncthreads();
    asm volatile("barrier.cluster.arrive.aligned;" ::: "memory");
    asm volatile("barrier.cluster.wait.aligned;" ::: "memory");

    const int jj = tid >> 2;
    const int bq = (tid & 3) * 2;
    const int kln = lane & 15;

    float br = 0.f, bz = 0.f, bn_ = 0.f;
    if (tid < 256) { br = bsm[jj]; bz = bsm[64 + jj]; bn_ = bsm[128 + jj]; }

    const uint32_t pushbase = (uint32_t)(OFF_HSM + jj * 32 + (((jj >> 2) & 1) << 4) + bq * 2);

    const char* w2p = smem + OFF_W2 + (size_t)wid * 8192 + lane * 16;

    float2 ho = make_float2(0.f, 0.f);

    for (int t = 0; t < TT; ++t) {
        const int p = t & 1;
        const uint32_t hbase = smb + (uint32_t)(OFF_HSM + p * 8192);

        float xr0, xz0, xn0, xr1, xz1, xn1;
        if (tid < 256) {
            size_t base = ((size_t)(g * 8 + bq) * TT + t) * GG + (s << 6) + jj;
            xr0 = g_xg[base];          xz0 = g_xg[base + 256];
            xn0 = g_xg[base + 512];
            xr1 = g_xg[base + (size_t)TT * GG];
            xz1 = g_xg[base + (size_t)TT * GG + 256];
            xn1 = g_xg[base + (size_t)TT * GG + 512];
        }

        float e0 = 0.f, e1 = 0.f, e2 = 0.f, e3 = 0.f;
        float o0 = 0.f, o1 = 0.f, o2 = 0.f, o3 = 0.f;

        // ---- GEMM-A: OWN slots (kt 12..15) — local data, no wait ----
#pragma unroll
        for (int kt = 12; kt < 16; ++kt) {
            int k0 = kt * 16 + kln;
            uint32_t rowHi = hbase + (uint32_t)(k0 * 32 + (((k0 >> 2) & 1) << 4));
            uint32_t rowLo = rowHi ^ 16u;
            uint32_t bh0, bh1, bl0, bl1;
            ldsm_x2t(bh0, bh1, rowHi);
            ldsm_x2t(bl0, bl1, rowLo);
            uint4 w2 = *(const uint4*)(w2p + kt * 512);
            if (kt & 1) {
                mma16816(o0, o1, o2, o3,
                         w1f[kt][0], w1f[kt][1], w1f[kt][2], w1f[kt][3], bh0, bh1);
                mma16816(o0, o1, o2, o3,
                         w1f[kt][0], w1f[kt][1], w1f[kt][2], w1f[kt][3], bl0, bl1);
                mma16816(o0, o1, o2, o3, w2.x, w2.y, w2.z, w2.w, bh0, bh1);
            } else {
                mma16816(e0, e1, e2, e3,
                         w1f[kt][0], w1f[kt][1], w1f[kt][2], w1f[kt][3], bh0, bh1);
                mma16816(e0, e1, e2, e3,
                         w1f[kt][0], w1f[kt][1], w1f[kt][2], w1f[kt][3], bl0, bl1);
                mma16816(e0, e1, e2, e3, w2.x, w2.y, w2.z, w2.w, bh0, bh1);
            }
        }

        if (t) mbar_waitc(smb + OFF_MBAR, (uint32_t)((t - 1) & 1));

        // ---- GEMM-B: peer slots (kt 0..11) ----
#pragma unroll
        for (int kt = 0; kt < 12; ++kt) {
            int k0 = kt * 16 + kln;
            uint32_t rowHi = hbase + (uint32_t)(k0 * 32 + (((k0 >> 2) & 1) << 4));
            uint32_t rowLo = rowHi ^ 16u;
            uint32_t bh0, bh1, bl0, bl1;
            ldsm_x2t(bh0, bh1, rowHi);
            ldsm_x2t(bl0, bl1, rowLo);
            uint4 w2 = *(const uint4*)(w2p + kt * 512);
            if (kt & 1) {
                mma16816(o0, o1, o2, o3,
                         w1f[kt][0], w1f[kt][1], w1f[kt][2], w1f[kt][3], bh0, bh1);
                mma16816(o0, o1, o2, o3,
                         w1f[kt][0], w1f[kt][1], w1f[kt][2], w1f[kt][3], bl0, bl1);
                mma16816(o0, o1, o2, o3, w2.x, w2.y, w2.z, w2.w, bh0, bh1);
            } else {
                mma16816(e0, e1, e2, e3,
                         w1f[kt][0], w1f[kt][1], w1f[kt][2], w1f[kt][3], bh0, bh1);
                mma16816(e0, e1, e2, e3,
                         w1f[kt][0], w1f[kt][1], w1f[kt][2], w1f[kt][3], bl0, bl1);
                mma16816(e0, e1, e2, e3, w2.x, w2.y, w2.z, w2.w, bh0, bh1);
            }
        }

        *(float2*)(ps + (wid * 16 + gq) * 8 + tq * 2)     = make_float2(e0 + o0, e1 + o1);
        *(float2*)(ps + (wid * 16 + gq + 8) * 8 + tq * 2) = make_float2(e2 + o2, e3 + o3);
        __syncthreads();

        float hw0 = 0.f, hw1 = 0.f;
        if (tid < 256) {
            float2 hr = *(const float2*)(ps + jj * 8 + bq);
            float2 hz = *(const float2*)(ps + (64 + jj) * 8 + bq);
            float2 hn = *(const float2*)(ps + (128 + jj) * 8 + bq);

            float r0g = __fdividef(1.f, 1.f + __expf(-(xr0 + hr.x + br)));
            float z0g = __fdividef(1.f, 1.f + __expf(-(xz0 + hz.x + bz)));
            float v0  = xn0 + r0g * (hn.x + bn_);
            float n0  = 1.f - 2.f * __fdividef(1.f, __expf(2.f * v0) + 1.f);
            hw0 = (1.f - z0g) * n0 + z0g * ho.x;

            float r1g = __fdividef(1.f, 1.f + __expf(-(xr1 + hr.y + br)));
            float z1g = __fdividef(1.f, 1.f + __expf(-(xz1 + hz.y + bz)));
            float v1  = xn1 + r1g * (hn.y + bn_);
            float n1  = 1.f - 2.f * __fdividef(1.f, __expf(2.f * v1) + 1.f);
            hw1 = (1.f - z1g) * n1 + z1g * ho.y;

            uint32_t hiw = pkbf(hw0, hw1);
            uint32_t low = pkbf(bfres(hw0), bfres(hw1));

            uint32_t base = smb + pushbase + (uint32_t)((1 - p) * 8192);
            asm volatile("st.shared.b32 [%0], %1;"
                         :: "r"(base + 6144u), "r"(hiw) : "memory");
            asm volatile("st.shared.b32 [%0], %1;"
                         :: "r"((base + 6144u) ^ 16u), "r"(low) : "memory");
#pragma unroll
            for (int rk = 0; rk < 4; ++rk) {
                if (rk == s) continue;
                uint32_t cslot = (uint32_t)(((s - rk - 1) & 3) << 11);
                uint32_t ra, rb;
                asm volatile("mapa.shared::cluster.u32 %0, %1, %2;"
                             : "=r"(ra) : "r"(base + cslot), "r"(rk));
                asm volatile("mapa.shared::cluster.u32 %0, %1, %2;"
                             : "=r"(rb) : "r"((base + cslot) ^ 16u), "r"(rk));
                asm volatile("st.shared::cluster.b32 [%0], %1;"
                             :: "r"(ra), "r"(hiw) : "memory");
                asm volatile("st.shared::cluster.b32 [%0], %1;"
                             :: "r"(rb), "r"(low) : "memory");
            }
            ho = make_float2(hw0, hw1);
        }
        __syncthreads();

        if (tid == 0) {
            asm volatile("fence.acq_rel.cluster;" ::: "memory");
#pragma unroll
            for (int rk = 0; rk < 4; ++rk) {
                uint32_t ra;
                asm volatile("mapa.shared::cluster.u32 %0, %1, %2;"
                             : "=r"(ra) : "r"(smb + OFF_MBAR), "r"(rk));
                asm volatile("mbarrier.arrive.shared::cluster.b64 _, [%0];"
                             :: "r"(ra) : "memory");
            }
        }
        if (tid < 256) {
            size_t ob = ((size_t)(g * 8 + bq) * TT + t) * HH + (s << 6) + jj;
            out[ob] = hw0;
            out[ob + (size_t)TT * HH] = hw1;
        }
    }

    asm volatile("barrier.cluster.arrive.aligned;" ::: "memory");
    asm volatile("barrier.cluster.wait.aligned;" ::: "memory");
}

// ---------------------------------------------------------------------------
extern "C" void kernel_launch(void* const* d_in, const int* in_sizes, int n_in,
                              void* d_out, int out_size)
{
    const float* x   = (const float*)d_in[0];
    const float* Wih = (const float*)d_in[1];
    const float* Whh = (const float*)d_in[2];
    const float* bih = (const float*)d_in[3];
    const float* bhh = (const float*)d_in[4];
    float* out = (float*)d_out;

    cudaFuncSetAttribute(xg_mma_kernel,
                         cudaFuncAttributeMaxDynamicSharedMemorySize, SM1_BYTES);
    cudaFuncSetAttribute(gru_seq_mma,
                         cudaFuncAttributeMaxDynamicSharedMemorySize, SM2_BYTES);

    xg_mma_kernel<<<1024, 256, SM1_BYTES>>>(x, Wih, bih);
    gru_seq_mma<<<128, TPB2, SM2_BYTES>>>(Whh, bhh, out);
}

// round 15
// speedup vs baseline: 1.5954x; 1.1524x over previous
#include <cuda_runtime.h>
#include <cuda_bf16.h>
#include <cstdint>
#include <cstddef>

#define BB 256
#define TT 512
#define II 128
#define HH 256
#define GG 768

typedef unsigned long long u64;

// ---------------- bf16 helpers ----------------
__device__ __forceinline__ uint32_t pkbf(float x, float y) {
    __nv_bfloat162 h = __floats2bfloat162_rn(x, y);
    return *(uint32_t*)&h;
}
__device__ __forceinline__ float bfres(float x) {   // x - bf16(x)
    return x - __bfloat162float(__float2bfloat16(x));
}
__device__ __forceinline__ void ldsm_x2t(uint32_t& r0, uint32_t& r1, uint32_t a) {
    asm volatile("ldmatrix.sync.aligned.m8n8.x2.trans.shared.b16 {%0,%1}, [%2];"
                 : "=r"(r0), "=r"(r1) : "r"(a));
}
__device__ __forceinline__ void mma16816(float& c0, float& c1, float& c2, float& c3,
                                         uint32_t a0, uint32_t a1, uint32_t a2, uint32_t a3,
                                         uint32_t b0, uint32_t b1) {
    asm("mma.sync.aligned.m16n8k16.row.col.f32.bf16.bf16.f32 "
        "{%0,%1,%2,%3}, {%4,%5,%6,%7}, {%8,%9}, {%0,%1,%2,%3};"
        : "+f"(c0), "+f"(c1), "+f"(c2), "+f"(c3)
        : "r"(a0), "r"(a1), "r"(a2), "r"(a3), "r"(b0), "r"(b1));
}

// ---------------------------------------------------------------------------
// FUSED GRU: input projection + recurrence in ONE persistent kernel.
// 32 clusters x 4 CTAs, 384 threads. Per step, each warp's GEMM covers
// K = 128 (x, staged 1 step ahead) + 256 (h, k-permuted own-slice overlap).
// n-gate ih contribution kept separate (ps rows 192-255).
// ---------------------------------------------------------------------------
#define TPB2 384

#define OFF_W2HH 0                        // 12*16*32*16 = 98304
#define OFF_W1IH 98304                    // 12*8*32*16  = 49152
#define OFF_W2IH 147456                   // 49152
#define OFF_HSM  196608                   // 2*256*32 = 16384
#define OFF_XSM  212992                   // 2*128*32 = 8192
#define OFF_PS   221184                   // 256*8*4  = 8192
#define OFF_BSM  229376                   // 256*4 = 1024
#define OFF_MBAR 230400                   // 8
#define SM2_BYTES 230408

__device__ __forceinline__ void mbar_waitc(uint32_t mbar, uint32_t parity) {
    uint32_t done;
    asm volatile(
        "{\n\t.reg .pred p;\n\t"
        "mbarrier.try_wait.parity.acquire.cluster.shared::cta.b64 p, [%1], %2;\n\t"
        "selp.b32 %0, 1, 0, p;\n\t}"
        : "=r"(done) : "r"(mbar), "r"(parity) : "memory");
    if (!done) {
        asm volatile(
            "{\n\t.reg .pred P1;\n\t"
            "W%=:\n\t"
            "mbarrier.try_wait.parity.acquire.cluster.shared::cta.b64 P1, [%0], %1, 0x989680;\n\t"
            "@P1 bra.uni D%=;\n\t"
            "bra.uni W%=;\n\t"
            "D%=:\n\t}"
            :: "r"(mbar), "r"(parity) : "memory");
    }
}

__global__ __launch_bounds__(TPB2, 1) __cluster_dims__(4, 1, 1)
void gru_fused(const float* __restrict__ x,
               const float* __restrict__ Wih,
               const float* __restrict__ Whh,
               const float* __restrict__ bih,
               const float* __restrict__ bhh,
               float* __restrict__ out)
{
    extern __shared__ char smem[];
    const uint32_t smb = (uint32_t)__cvta_generic_to_shared(smem);
    float* ps  = (float*)(smem + OFF_PS);
    float* bsm = (float*)(smem + OFF_BSM);

    const int tid  = threadIdx.x;
    const int wid  = tid >> 5;
    const int lane = tid & 31;
    const int gq   = lane >> 2;
    const int tq   = lane & 3;
    uint32_t srank;
    asm("mov.u32 %0, %%cluster_ctarank;" : "=r"(srank));
    const int s = (int)srank;
    const int g = blockIdx.x >> 2;
    const int kperm = ((s + 1) << 6);

    // gate-row indices for this warp's two m8 rows
    const int row0 = wid * 16 + gq;
    const int row1 = row0 + 8;
    const int r0g = ((row0 >> 6) << 8) + (s << 6) + (row0 & 63);
    const int r1g = ((row1 >> 6) << 8) + (s << 6) + (row1 & 63);

    // ---- init W_hh: W1 frags -> regs, W2 frags -> SMEM (permuted cols) ----
    uint32_t w1f[16][4];
    {
        const float* W0 = Whh + (size_t)r0g * 256;
        const float* W1 = Whh + (size_t)r1g * 256;
#pragma unroll
        for (int kt = 0; kt < 16; ++kt) {
            int c0 = (kt * 16 + tq * 2 + kperm) & 255;
            float w00 = W0[c0],     w01 = W0[c0 + 1];
            float w10 = W1[c0],     w11 = W1[c0 + 1];
            float w02 = W0[c0 + 8], w03 = W0[c0 + 9];
            float w12 = W1[c0 + 8], w13 = W1[c0 + 9];
            w1f[kt][0] = pkbf(w00, w01);
            w1f[kt][1] = pkbf(w10, w11);
            w1f[kt][2] = pkbf(w02, w03);
            w1f[kt][3] = pkbf(w12, w13);
            uint4 w2;
            w2.x = pkbf(bfres(w00), bfres(w01));
            w2.y = pkbf(bfres(w10), bfres(w11));
            w2.z = pkbf(bfres(w02), bfres(w03));
            w2.w = pkbf(bfres(w12), bfres(w13));
            *(uint4*)(smem + OFF_W2HH + (((wid * 16 + kt) * 32) + lane) * 16) = w2;
        }
    }
    // ---- init W_ih: both split terms -> SMEM (no permutation, K=128) ----
    {
        const float* W0 = Wih + (size_t)r0g * 128;
        const float* W1 = Wih + (size_t)r1g * 128;
#pragma unroll
        for (int kt = 0; kt < 8; ++kt) {
            int c0 = kt * 16 + tq * 2;
            float w00 = W0[c0],     w01 = W0[c0 + 1];
            float w10 = W1[c0],     w11 = W1[c0 + 1];
            float w02 = W0[c0 + 8], w03 = W0[c0 + 9];
            float w12 = W1[c0 + 8], w13 = W1[c0 + 9];
            uint4 w1v, w2v;
            w1v.x = pkbf(w00, w01); w1v.y = pkbf(w10, w11);
            w1v.z = pkbf(w02, w03); w1v.w = pkbf(w12, w13);
            w2v.x = pkbf(bfres(w00), bfres(w01));
            w2v.y = pkbf(bfres(w10), bfres(w11));
            w2v.z = pkbf(bfres(w02), bfres(w03));
            w2v.w = pkbf(bfres(w12), bfres(w13));
            uint32_t o = (uint32_t)(((wid * 8 + kt) * 32 + lane) * 16);
            *(uint4*)(smem + OFF_W1IH + o) = w1v;
            *(uint4*)(smem + OFF_W2IH + o) = w2v;
        }
    }
    // ---- biases: [r: bih+bhh][z: bih+bhh][n: bhh][n: bih] ----
    if (tid < 192) {
        int grow = ((tid >> 6) << 8) + (s << 6) + (tid & 63);
        bsm[tid] = (tid < 128) ? (bhh[grow] + bih[grow]) : bhh[grow];
    } else if (tid < 256) {
        int grow = 512 + (s << 6) + (tid - 192);
        bsm[tid] = bih[grow];
    }
    for (int i = tid; i < 16384 / 4; i += TPB2)
        ((float*)(smem + OFF_HSM))[i] = 0.f;
    if (tid == 0) {
        asm volatile("mbarrier.init.shared.b64 [%0], %1;"
                     :: "r"(smb + OFF_MBAR), "r"(4u) : "memory");
    }

    // ---- prologue: stage x(0) into xsm[0] ----
    const int sk  = tid & 127;            // staging k
    const int sbp = tid >> 7;             // staging batch-pair base (0/1), +2
    if (tid < 256) {
#pragma unroll
        for (int e = 0; e < 2; ++e) {
            int bp = sbp + 2 * e;
            float v0 = x[((size_t)(g * 8 + 2 * bp) * TT) * II + sk];
            float v1 = x[((size_t)(g * 8 + 2 * bp + 1) * TT) * II + sk];
            uint32_t hi = pkbf(v0, v1);
            uint32_t lo = pkbf(bfres(v0), bfres(v1));
            uint32_t a = smb + (uint32_t)(OFF_XSM + sk * 32 +
                                          (((sk >> 2) & 1) << 4) + bp * 4);
            asm volatile("st.shared.b32 [%0], %1;" :: "r"(a), "r"(hi) : "memory");
            asm volatile("st.shared.b32 [%0], %1;" :: "r"(a ^ 16u), "r"(lo) : "memory");
        }
    }
    __syncthreads();
    asm volatile("barrier.cluster.arrive.aligned;" ::: "memory");
    asm volatile("barrier.cluster.wait.aligned;" ::: "memory");

    const int jj = tid >> 2;              // gate j (tid<256)
    const int bq = (tid & 3) * 2;         // gate batch pair
    const int kln = lane & 15;

    float br = 0.f, bz = 0.f, bhn = 0.f, bxn = 0.f;
    if (tid < 256) {
        br  = bsm[jj];       bz  = bsm[64 + jj];
        bhn = bsm[128 + jj]; bxn = bsm[192 + jj];
    }

    const uint32_t pushbase = (uint32_t)(OFF_HSM + jj * 32 + (((jj >> 2) & 1) << 4) + bq * 2);

    const char* w2p   = smem + OFF_W2HH + (size_t)wid * 8192 + lane * 16;
    const char* w1ihp = smem + OFF_W1IH + (size_t)wid * 4096 + lane * 16;
    const char* w2ihp = smem + OFF_W2IH + (size_t)wid * 4096 + lane * 16;

    float2 ho = make_float2(0.f, 0.f);

    for (int t = 0; t < TT; ++t) {
        const int p = t & 1;
        const uint32_t hbase = smb + (uint32_t)(OFF_HSM + p * 8192);
        const uint32_t xbase = smb + (uint32_t)(OFF_XSM + p * 4096);

        // prefetch x(t+1) (LDG hidden under GEMM)
        float xp0 = 0.f, xp1 = 0.f, xp2 = 0.f, xp3 = 0.f;
        if (tid < 256 && t + 1 < TT) {
            xp0 = x[((size_t)(g * 8 + 2 * sbp) * TT + t + 1) * II + sk];
            xp1 = x[((size_t)(g * 8 + 2 * sbp + 1) * TT + t + 1) * II + sk];
            xp2 = x[((size_t)(g * 8 + 2 * (sbp + 2)) * TT + t + 1) * II + sk];
            xp3 = x[((size_t)(g * 8 + 2 * (sbp + 2) + 1) * TT + t + 1) * II + sk];
        }

        float e0 = 0.f, e1 = 0.f, e2 = 0.f, e3 = 0.f;   // hh even kt
        float o0 = 0.f, o1 = 0.f, o2 = 0.f, o3 = 0.f;   // hh odd kt
        float q0 = 0.f, q1 = 0.f, q2 = 0.f, q3 = 0.f;   // ih chain

        // ---- GEMM-ih: x(t) from xsm[p] — fully local, no wait ----
#pragma unroll
        for (int kt = 0; kt < 8; ++kt) {
            int k0 = kt * 16 + kln;
            uint32_t rowHi = xbase + (uint32_t)(k0 * 32 + (((k0 >> 2) & 1) << 4));
            uint32_t rowLo = rowHi ^ 16u;
            uint32_t bh0, bh1, bl0, bl1;
            ldsm_x2t(bh0, bh1, rowHi);
            ldsm_x2t(bl0, bl1, rowLo);
            uint4 w1 = *(const uint4*)(w1ihp + kt * 512);
            uint4 w2 = *(const uint4*)(w2ihp + kt * 512);
            mma16816(q0, q1, q2, q3, w1.x, w1.y, w1.z, w1.w, bh0, bh1);
            mma16816(q0, q1, q2, q3, w1.x, w1.y, w1.z, w1.w, bl0, bl1);
            mma16816(q0, q1, q2, q3, w2.x, w2.y, w2.z, w2.w, bh0, bh1);
        }

        // ---- GEMM-A: OWN hh slots (kt 12..15) — local, no wait ----
#pragma unroll
        for (int kt = 12; kt < 16; ++kt) {
            int k0 = kt * 16 + kln;
            uint32_t rowHi = hbase + (uint32_t)(k0 * 32 + (((k0 >> 2) & 1) << 4));
            uint32_t rowLo = rowHi ^ 16u;
            uint32_t bh0, bh1, bl0, bl1;
            ldsm_x2t(bh0, bh1, rowHi);
            ldsm_x2t(bl0, bl1, rowLo);
            uint4 w2 = *(const uint4*)(w2p + kt * 512);
            if (kt & 1) {
                mma16816(o0, o1, o2, o3,
                         w1f[kt][0], w1f[kt][1], w1f[kt][2], w1f[kt][3], bh0, bh1);
                mma16816(o0, o1, o2, o3,
                         w1f[kt][0], w1f[kt][1], w1f[kt][2], w1f[kt][3], bl0, bl1);
                mma16816(o0, o1, o2, o3, w2.x, w2.y, w2.z, w2.w, bh0, bh1);
            } else {
                mma16816(e0, e1, e2, e3,
                         w1f[kt][0], w1f[kt][1], w1f[kt][2], w1f[kt][3], bh0, bh1);
                mma16816(e0, e1, e2, e3,
                         w1f[kt][0], w1f[kt][1], w1f[kt][2], w1f[kt][3], bl0, bl1);
                mma16816(e0, e1, e2, e3, w2.x, w2.y, w2.z, w2.w, bh0, bh1);
            }
        }

        // ---- wait for peers' step t-1 pushes ----
        if (t) mbar_waitc(smb + OFF_MBAR, (uint32_t)((t - 1) & 1));

        // ---- GEMM-B: peer hh slots (kt 0..11) ----
#pragma unroll
        for (int kt = 0; kt < 12; ++kt) {
            int k0 = kt * 16 + kln;
            uint32_t rowHi = hbase + (uint32_t)(k0 * 32 + (((k0 >> 2) & 1) << 4));
            uint32_t rowLo = rowHi ^ 16u;
            uint32_t bh0, bh1, bl0, bl1;
            ldsm_x2t(bh0, bh1, rowHi);
            ldsm_x2t(bl0, bl1, rowLo);
            uint4 w2 = *(const uint4*)(w2p + kt * 512);
            if (kt & 1) {
                mma16816(o0, o1, o2, o3,
                         w1f[kt][0], w1f[kt][1], w1f[kt][2], w1f[kt][3], bh0, bh1);
                mma16816(o0, o1, o2, o3,
                         w1f[kt][0], w1f[kt][1], w1f[kt][2], w1f[kt][3], bl0, bl1);
                mma16816(o0, o1, o2, o3, w2.x, w2.y, w2.z, w2.w, bh0, bh1);
            } else {
                mma16816(e0, e1, e2, e3,
                         w1f[kt][0], w1f[kt][1], w1f[kt][2], w1f[kt][3], bh0, bh1);
                mma16816(e0, e1, e2, e3,
                         w1f[kt][0], w1f[kt][1], w1f[kt][2], w1f[kt][3], bl0, bl1);
                mma16816(e0, e1, e2, e3, w2.x, w2.y, w2.z, w2.w, bh0, bh1);
            }
        }

        // ---- deposit: r/z rows fuse ih; n rows keep ih separate ----
        {
            float v0 = e0 + o0, v1 = e1 + o1, v2 = e2 + o2, v3 = e3 + o3;
            if (wid < 8) { v0 += q0; v1 += q1; v2 += q2; v3 += q3; }
            *(float2*)(ps + row0 * 8 + tq * 2) = make_float2(v0, v1);
            *(float2*)(ps + row1 * 8 + tq * 2) = make_float2(v2, v3);
            if (wid >= 8) {
                *(float2*)(ps + (row0 + 64) * 8 + tq * 2) = make_float2(q0, q1);
                *(float2*)(ps + (row1 + 64) * 8 + tq * 2) = make_float2(q2, q3);
            }
        }
        __syncthreads();

        // ---- gates ----
        float hw0 = 0.f, hw1 = 0.f;
        if (tid < 256) {
            float2 rz = *(const float2*)(ps + jj * 8 + bq);          // x+h (r)
            float2 zz = *(const float2*)(ps + (64 + jj) * 8 + bq);   // x+h (z)
            float2 hn = *(const float2*)(ps + (128 + jj) * 8 + bq);  // h only
            float2 xn = *(const float2*)(ps + (192 + jj) * 8 + bq);  // x only

            float r0g_ = __fdividef(1.f, 1.f + __expf(-(rz.x + br)));
            float z0g_ = __fdividef(1.f, 1.f + __expf(-(zz.x + bz)));
            float v0   = xn.x + bxn + r0g_ * (hn.x + bhn);
            float n0   = 1.f - 2.f * __fdividef(1.f, __expf(2.f * v0) + 1.f);
            hw0 = (1.f - z0g_) * n0 + z0g_ * ho.x;

            float r1g_ = __fdividef(1.f, 1.f + __expf(-(rz.y + br)));
            float z1g_ = __fdividef(1.f, 1.f + __expf(-(zz.y + bz)));
            float v1   = xn.y + bxn + r1g_ * (hn.y + bhn);
            float n1   = 1.f - 2.f * __fdividef(1.f, __expf(2.f * v1) + 1.f);
            hw1 = (1.f - z1g_) * n1 + z1g_ * ho.y;

            uint32_t hiw = pkbf(hw0, hw1);
            uint32_t low = pkbf(bfres(hw0), bfres(hw1));

            uint32_t base = smb + pushbase + (uint32_t)((1 - p) * 8192);
            asm volatile("st.shared.b32 [%0], %1;"
                         :: "r"(base + 6144u), "r"(hiw) : "memory");
            asm volatile("st.shared.b32 [%0], %1;"
                         :: "r"((base + 6144u) ^ 16u), "r"(low) : "memory");
#pragma unroll
            for (int rk = 0; rk < 4; ++rk) {
                if (rk == s) continue;
                uint32_t cslot = (uint32_t)(((s - rk - 1) & 3) << 11);
                uint32_t ra, rb;
                asm volatile("mapa.shared::cluster.u32 %0, %1, %2;"
                             : "=r"(ra) : "r"(base + cslot), "r"(rk));
                asm volatile("mapa.shared::cluster.u32 %0, %1, %2;"
                             : "=r"(rb) : "r"((base + cslot) ^ 16u), "r"(rk));
                asm volatile("st.shared::cluster.b32 [%0], %1;"
                             :: "r"(ra), "r"(hiw) : "memory");
                asm volatile("st.shared::cluster.b32 [%0], %1;"
                             :: "r"(rb), "r"(low) : "memory");
            }
            ho = make_float2(hw0, hw1);

            // ---- stage x(t+1) into xsm[1-p] ----
            if (t + 1 < TT) {
                uint32_t xa = smb + (uint32_t)(OFF_XSM + (1 - p) * 4096 +
                              sk * 32 + (((sk >> 2) & 1) << 4));
                uint32_t h0 = pkbf(xp0, xp1);
                uint32_t l0 = pkbf(bfres(xp0), bfres(xp1));
                uint32_t h1 = pkbf(xp2, xp3);
                uint32_t l1 = pkbf(bfres(xp2), bfres(xp3));
                uint32_t a0 = xa + (uint32_t)(sbp * 4);
                uint32_t a1 = xa + (uint32_t)((sbp + 2) * 4);
                asm volatile("st.shared.b32 [%0], %1;" :: "r"(a0), "r"(h0) : "memory");
                asm volatile("st.shared.b32 [%0], %1;" :: "r"(a0 ^ 16u), "r"(l0) : "memory");
                asm volatile("st.shared.b32 [%0], %1;" :: "r"(a1), "r"(h1) : "memory");
                asm volatile("st.shared.b32 [%0], %1;" :: "r"(a1 ^ 16u), "r"(l1) : "memory");
            }
        }
        __syncthreads();

        // ---- signal all ranks, THEN write outputs ----
        if (tid == 0) {
            asm volatile("fence.acq_rel.cluster;" ::: "memory");
#pragma unroll
            for (int rk = 0; rk < 4; ++rk) {
                uint32_t ra;
                asm volatile("mapa.shared::cluster.u32 %0, %1, %2;"
                             : "=r"(ra) : "r"(smb + OFF_MBAR), "r"(rk));
                asm volatile("mbarrier.arrive.shared::cluster.b64 _, [%0];"
                             :: "r"(ra) : "memory");
            }
        }
        if (tid < 256) {
            size_t ob = ((size_t)(g * 8 + bq) * TT + t) * HH + (s << 6) + jj;
            out[ob] = hw0;
            out[ob + (size_t)TT * HH] = hw1;
        }
    }

    asm volatile("barrier.cluster.arrive.aligned;" ::: "memory");
    asm volatile("barrier.cluster.wait.aligned;" ::: "memory");
}

// ---------------------------------------------------------------------------
extern "C" void kernel_launch(void* const* d_in, const int* in_sizes, int n_in,
                              void* d_out, int out_size)
{
    const float* x   = (const float*)d_in[0];
    const float* Wih = (const float*)d_in[1];
    const float* Whh = (const float*)d_in[2];
    const float* bih = (const float*)d_in[3];
    const float* bhh = (const float*)d_in[4];
    float* out = (float*)d_out;

    cudaFuncSetAttribute(gru_fused,
                         cudaFuncAttributeMaxDynamicSharedMemorySize, SM2_BYTES);

    gru_fused<<<128, TPB2, SM2_BYTES>>>(x, Wih, Whh, bih, bhh, out);
}